// round 1
// baseline (speedup 1.0000x reference)
#include <cuda_runtime.h>

namespace {
constexpr int B = 4, H = 16, S = 2048, D = 64;
constexpr int BH = B * H;
constexpr int TQ = 16;         // q rows per block
constexpr int TK = 256;        // k/v rows per smem tile
constexpr int THREADS = 256;
constexpr int KV_STRIDE = 68;  // padded row stride (floats) for K/V tile
constexpr int Q_STRIDE = 68;

// shared memory layout (float offsets)
constexpr int SC_OFF = 0;                        // scores: TQ x S
constexpr int KV_OFF = SC_OFF + TQ * S;          // K/V tile: TK x KV_STRIDE (reused for partials)
constexpr int QS_OFF = KV_OFF + TK * KV_STRIDE;  // Q tile: TQ x Q_STRIDE
constexpr int MS_OFF = QS_OFF + TQ * Q_STRIDE;   // mask row: S
constexpr int SMEM_FLOATS = MS_OFF + S;
constexpr unsigned SMEM_BYTES = SMEM_FLOATS * sizeof(float);  // 213,248 B
}

__global__ __launch_bounds__(THREADS, 1)
void attn_kernel(const float* __restrict__ q, const float* __restrict__ k,
                 const float* __restrict__ v, const int* __restrict__ mask,
                 float* __restrict__ out, float* __restrict__ p_attn)
{
    extern __shared__ float sm[];
    float* sc = sm + SC_OFF;
    float* kv = sm + KV_OFF;
    float* qs = sm + QS_OFF;
    float* ms = sm + MS_OFF;

    const int tid = threadIdx.x;
    const int qt  = blockIdx.x;     // 0..127  (q tile) — fast dim so concurrent blocks share bh (L2 reuse of K/V)
    const int bh  = blockIdx.y;     // 0..63
    const int b   = bh / H;
    const int q0  = qt * TQ;
    const size_t bh_off = (size_t)bh * S * D;

    // ---- load Q tile (pre-scaled by 1/sqrt(D)) ----
    {
        int row = tid >> 4;             // 0..15
        int c4  = (tid & 15) << 2;      // 0..60
        float4 t = *reinterpret_cast<const float4*>(q + bh_off + (size_t)(q0 + row) * D + c4);
        const float scl = 0.125f;
        float* dst = qs + row * Q_STRIDE + c4;
        dst[0] = t.x * scl; dst[1] = t.y * scl; dst[2] = t.z * scl; dst[3] = t.w * scl;
    }
    // ---- load mask row as 0/1 floats ----
    for (int i = tid; i < S; i += THREADS)
        ms[i] = (mask[b * S + i] != 0) ? 1.0f : 0.0f;

    __syncthreads();

    // ================= Phase 1: scores = (Q/sqrt(D)) K^T =================
    const int lane64 = tid & 63;   // k column base within tile (strided by 64)
    const int qg     = tid >> 6;   // 0..3 -> q rows qg*4 .. qg*4+3

    for (int t0 = 0; t0 < S; t0 += TK) {
        // cooperative coalesced load of K tile (TK x D)
        #pragma unroll
        for (int j = 0; j < (TK * D / 4) / THREADS; ++j) {   // 16 float4 per thread
            int fi  = tid + j * THREADS;
            int row = fi >> 4;
            int c4  = (fi & 15) << 2;
            float4 t = *reinterpret_cast<const float4*>(k + bh_off + (size_t)(t0 + row) * D + c4);
            float* dst = kv + row * KV_STRIDE + c4;
            dst[0] = t.x; dst[1] = t.y; dst[2] = t.z; dst[3] = t.w;
        }
        __syncthreads();

        float acc[4][4];
        #pragma unroll
        for (int i = 0; i < 4; ++i)
            #pragma unroll
            for (int j = 0; j < 4; ++j) acc[i][j] = 0.f;

        #pragma unroll 4
        for (int d4 = 0; d4 < D; d4 += 4) {
            float4 qv[4], kt[4];
            #pragma unroll
            for (int i = 0; i < 4; ++i)   // broadcast within warp (qg constant per warp)
                qv[i] = *reinterpret_cast<const float4*>(qs + (qg * 4 + i) * Q_STRIDE + d4);
            #pragma unroll
            for (int j = 0; j < 4; ++j)   // lane-strided rows: conflict-free (stride 68)
                kt[j] = *reinterpret_cast<const float4*>(kv + (lane64 + j * 64) * KV_STRIDE + d4);
            #pragma unroll
            for (int i = 0; i < 4; ++i)
                #pragma unroll
                for (int j = 0; j < 4; ++j) {
                    acc[i][j] += qv[i].x * kt[j].x;
                    acc[i][j] += qv[i].y * kt[j].y;
                    acc[i][j] += qv[i].z * kt[j].z;
                    acc[i][j] += qv[i].w * kt[j].w;
                }
        }
        #pragma unroll
        for (int i = 0; i < 4; ++i)
            #pragma unroll
            for (int j = 0; j < 4; ++j)
                sc[(qg * 4 + i) * S + t0 + lane64 + j * 64] = acc[i][j];
        __syncthreads();
    }

    // ================= Phase 2: masked softmax + p_attn store =================
    {
        const int w = tid >> 5;   // warp 0..7 handles rows 2w, 2w+1
        const int l = tid & 31;
        #pragma unroll
        for (int rr = 0; rr < 2; ++rr) {
            const int r = w * 2 + rr;
            float* row = sc + r * S;
            float ssum = 0.f;
            for (int c = l * 4; c < S; c += 128) {
                float4 sv = *reinterpret_cast<const float4*>(row + c);
                const float4 mv = *reinterpret_cast<const float4*>(ms + c);
                sv.x = mv.x * __expf(sv.x);
                sv.y = mv.y * __expf(sv.y);
                sv.z = mv.z * __expf(sv.z);
                sv.w = mv.w * __expf(sv.w);
                *reinterpret_cast<float4*>(row + c) = sv;
                ssum += (sv.x + sv.y) + (sv.z + sv.w);
            }
            #pragma unroll
            for (int o = 16; o; o >>= 1) ssum += __shfl_xor_sync(0xffffffffu, ssum, o);
            const float inv = 1.0f / ssum;
            float* gp = p_attn + ((size_t)bh * S + q0 + r) * S;
            for (int c = l * 4; c < S; c += 128) {
                float4 ev = *reinterpret_cast<float4*>(row + c);
                ev.x *= inv; ev.y *= inv; ev.z *= inv; ev.w *= inv;
                *reinterpret_cast<float4*>(row + c) = ev;   // normalized P kept for phase 3
                *reinterpret_cast<float4*>(gp + c) = ev;    // coalesced 512B stores
            }
        }
    }

    // ================= Phase 3: out = P V  (4-way k-split) =================
    const int g  = tid >> 6;             // k-quarter 0..3 within each tile
    const int l2 = tid & 63;
    const int qb = (l2 >> 4) * 4;        // q row base: 0,4,8,12
    const int db = (l2 & 15) * 4;        // d base: 0..60

    float oacc[4][4];
    #pragma unroll
    for (int i = 0; i < 4; ++i)
        #pragma unroll
        for (int c = 0; c < 4; ++c) oacc[i][c] = 0.f;

    for (int t0 = 0; t0 < S; t0 += TK) {
        __syncthreads();   // previous tile (or phase-2 P) fully consumed before overwriting kv
        #pragma unroll
        for (int j = 0; j < (TK * D / 4) / THREADS; ++j) {
            int fi  = tid + j * THREADS;
            int row = fi >> 4;
            int c4  = (fi & 15) << 2;
            float4 t = *reinterpret_cast<const float4*>(v + bh_off + (size_t)(t0 + row) * D + c4);
            float* dst = kv + row * KV_STRIDE + c4;
            dst[0] = t.x; dst[1] = t.y; dst[2] = t.z; dst[3] = t.w;
        }
        __syncthreads();

        #pragma unroll 4
        for (int kk = 0; kk < 64; kk += 4) {
            const int kr = g * 64 + kk;
            float4 pv[4];
            float  vvf[4][4];
            #pragma unroll
            for (int i = 0; i < 4; ++i)   // broadcast within 8-lane phase
                pv[i] = *reinterpret_cast<const float4*>(sc + (qb + i) * S + t0 + kr);
            #pragma unroll
            for (int j = 0; j < 4; ++j) { // conflict-free: db spans distinct 16B chunks
                float4 t = *reinterpret_cast<const float4*>(kv + (kr + j) * KV_STRIDE + db);
                vvf[j][0] = t.x; vvf[j][1] = t.y; vvf[j][2] = t.z; vvf[j][3] = t.w;
            }
            #pragma unroll
            for (int i = 0; i < 4; ++i) {
                const float4 p = pv[i];
                #pragma unroll
                for (int c = 0; c < 4; ++c) {
                    oacc[i][c] += p.x * vvf[0][c];
                    oacc[i][c] += p.y * vvf[1][c];
                    oacc[i][c] += p.z * vvf[2][c];
                    oacc[i][c] += p.w * vvf[3][c];
                }
            }
        }
    }

    __syncthreads();   // all V/P reads done; reuse kv as partial-sum buffer
    #pragma unroll
    for (int i = 0; i < 4; ++i)
        #pragma unroll
        for (int c = 0; c < 4; ++c)
            kv[g * (TQ * D) + (qb + i) * D + db + c] = oacc[i][c];
    __syncthreads();

    {
        const int o = tid * 4;           // output element base (0..1020)
        float4 r0 = *reinterpret_cast<const float4*>(kv + o);
        float4 r1 = *reinterpret_cast<const float4*>(kv + TQ * D + o);
        float4 r2 = *reinterpret_cast<const float4*>(kv + 2 * TQ * D + o);
        float4 r3 = *reinterpret_cast<const float4*>(kv + 3 * TQ * D + o);
        float4 rs;
        rs.x = (r0.x + r1.x) + (r2.x + r3.x);
        rs.y = (r0.y + r1.y) + (r2.y + r3.y);
        rs.z = (r0.z + r1.z) + (r2.z + r3.z);
        rs.w = (r0.w + r1.w) + (r2.w + r3.w);
        const int qi = o >> 6;
        const int d  = o & 63;
        *reinterpret_cast<float4*>(out + bh_off + (size_t)(q0 + qi) * D + d) = rs;
    }
}

extern "C" void kernel_launch(void* const* d_in, const int* in_sizes, int n_in,
                              void* d_out, int out_size) {
    const float* q = (const float*)d_in[0];
    const float* k = (const float*)d_in[1];
    const float* v = (const float*)d_in[2];
    const int* mask = (const int*)d_in[3];

    float* out = (float*)d_out;
    float* p_attn = out + (size_t)B * H * S * D;   // outputs concatenated: (out, p_attn)

    cudaFuncSetAttribute(attn_kernel, cudaFuncAttributeMaxDynamicSharedMemorySize, SMEM_BYTES);
    dim3 grid(S / TQ, BH);
    attn_kernel<<<grid, THREADS, SMEM_BYTES>>>(q, k, v, mask, out, p_attn);
}

// round 3
// speedup vs baseline: 2.2278x; 2.2278x over previous
#include <cuda_runtime.h>
#include <cuda_bf16.h>
#include <cstdint>

namespace {
constexpr int Bn = 4, Hn = 16, S = 2048, Dh = 64;
constexpr int BH = Bn * Hn;
constexpr int MQ = 128;           // q rows per CTA
constexpr int NK = 128;           // keys per tile
constexpr int NT = S / NK;        // 16
constexpr int THREADS = 256;      // 8 warps, one 16-row m-tile each
constexpr int NELEM = BH * S * Dh;   // 8,388,608

// dynamic smem byte offsets (all 2048-aligned)
constexpr int OFF_Q   = 0;              // [2 hi/lo][128][64] bf16 = 32768
constexpr int OFF_K   = OFF_Q + 32768;  // [2][128][64] bf16     = 32768
constexpr int OFF_V   = OFF_K + 32768;  // [2][2 kb][64][64] bf16= 32768
constexpr int OFF_P   = OFF_V + 32768;  // [8 w][2][2 kb][16][64]= 65536
constexpr int OFF_MS  = OFF_P + 65536;  // 2048 f32              = 8192
constexpr int OFF_INV = OFF_MS + 8192;  // 128 f32               = 512
constexpr unsigned SMEM_BYTES = OFF_INV + 512;   // 173,568 B
}

// bf16 hi/lo scratch (static device arrays — no runtime allocation)
__device__ __nv_bfloat16 g_Qhi[NELEM], g_Qlo[NELEM];
__device__ __nv_bfloat16 g_Khi[NELEM], g_Klo[NELEM];
__device__ __nv_bfloat16 g_VThi[NELEM], g_VTlo[NELEM];   // [bh][d][s]

__device__ __forceinline__ uint32_t s2u(const void* p) {
    uint32_t a;
    asm("{ .reg .u64 t; cvta.to.shared.u64 t, %1; cvt.u32.u64 %0, t; }" : "=r"(a) : "l"(p));
    return a;
}
__device__ __forceinline__ uint32_t swz(uint32_t o) { return o ^ ((o >> 3) & 0x70); }

#define LDSM4(r, a) \
    asm volatile("ldmatrix.sync.aligned.m8n8.x4.shared.b16 {%0,%1,%2,%3},[%4];" \
                 : "=r"((r)[0]), "=r"((r)[1]), "=r"((r)[2]), "=r"((r)[3]) : "r"(a))

__device__ __forceinline__ void mma_bf16(float c[4], const uint32_t a[4],
                                         uint32_t b0, uint32_t b1) {
    asm volatile(
        "mma.sync.aligned.m16n8k16.row.col.f32.bf16.bf16.f32 "
        "{%0,%1,%2,%3},{%4,%5,%6,%7},{%8,%9},{%0,%1,%2,%3};"
        : "+f"(c[0]), "+f"(c[1]), "+f"(c[2]), "+f"(c[3])
        : "r"(a[0]), "r"(a[1]), "r"(a[2]), "r"(a[3]), "r"(b0), "r"(b1));
}

__device__ __forceinline__ void fsplit(float x, __nv_bfloat16& h, __nv_bfloat16& l) {
    h = __float2bfloat16_rn(x);
    l = __float2bfloat16_rn(x - __bfloat162float(h));
}
__device__ __forceinline__ uint32_t pack_hi(float x, float y) {
    __nv_bfloat162 t;
    t.x = __float2bfloat16_rn(x);
    t.y = __float2bfloat16_rn(y);
    return *reinterpret_cast<uint32_t*>(&t);
}
__device__ __forceinline__ uint32_t pack_lo(float x, float y) {
    __nv_bfloat162 t;
    t.x = __float2bfloat16_rn(x - __bfloat162float(__float2bfloat16_rn(x)));
    t.y = __float2bfloat16_rn(y - __bfloat162float(__float2bfloat16_rn(y)));
    return *reinterpret_cast<uint32_t*>(&t);
}

// ---------------- pre-kernels ----------------
__global__ void conv_qk(const float* __restrict__ q, const float* __restrict__ k) {
    size_t i4 = (size_t)blockIdx.x * blockDim.x + threadIdx.x;  // 0..NELEM/4-1
    size_t e = i4 * 4;
    float4 qv = *reinterpret_cast<const float4*>(q + e);
    float4 kv = *reinterpret_cast<const float4*>(k + e);
    qv.x *= 0.125f; qv.y *= 0.125f; qv.z *= 0.125f; qv.w *= 0.125f;   // 1/sqrt(64)
    __nv_bfloat16 h, l;
    fsplit(qv.x, h, l); g_Qhi[e + 0] = h; g_Qlo[e + 0] = l;
    fsplit(qv.y, h, l); g_Qhi[e + 1] = h; g_Qlo[e + 1] = l;
    fsplit(qv.z, h, l); g_Qhi[e + 2] = h; g_Qlo[e + 2] = l;
    fsplit(qv.w, h, l); g_Qhi[e + 3] = h; g_Qlo[e + 3] = l;
    fsplit(kv.x, h, l); g_Khi[e + 0] = h; g_Klo[e + 0] = l;
    fsplit(kv.y, h, l); g_Khi[e + 1] = h; g_Klo[e + 1] = l;
    fsplit(kv.z, h, l); g_Khi[e + 2] = h; g_Klo[e + 2] = l;
    fsplit(kv.w, h, l); g_Khi[e + 3] = h; g_Klo[e + 3] = l;
}

__global__ void conv_vt(const float* __restrict__ v) {
    __shared__ float t[32][33];
    const int bh = blockIdx.z, s0 = blockIdx.x * 32, d0 = blockIdx.y * 32;
    const int tx = threadIdx.x, ty = threadIdx.y;   // (32, 8)
    #pragma unroll
    for (int j = 0; j < 4; ++j)
        t[ty + 8 * j][tx] = v[((size_t)bh * S + s0 + ty + 8 * j) * Dh + d0 + tx];
    __syncthreads();
    #pragma unroll
    for (int j = 0; j < 4; ++j) {
        float x = t[tx][ty + 8 * j];
        __nv_bfloat16 h, l;
        fsplit(x, h, l);
        size_t o = ((size_t)bh * Dh + d0 + ty + 8 * j) * S + s0 + tx;
        g_VThi[o] = h; g_VTlo[o] = l;
    }
}

// ---------------- main kernel ----------------
namespace {

__device__ __forceinline__ void load_k_tile(char* sm, int tid, int bh, int t0) {
    #pragma unroll
    for (int buf = 0; buf < 2; ++buf) {
        const __nv_bfloat16* src = buf ? g_Klo : g_Khi;
        #pragma unroll
        for (int i = 0; i < 4; ++i) {
            int fi = tid + i * THREADS;        // 1024 16B chunks
            int row = fi >> 3, c8 = fi & 7;
            uint4 u = *reinterpret_cast<const uint4*>(
                src + ((size_t)bh * S + t0 + row) * Dh + c8 * 8);
            *reinterpret_cast<uint4*>(sm + OFF_K + buf * 16384 +
                                      swz((uint32_t)(row * 128 + c8 * 16))) = u;
        }
    }
}
__device__ __forceinline__ void load_v_tile(char* sm, int tid, int bh, int t0) {
    #pragma unroll
    for (int buf = 0; buf < 2; ++buf) {
        const __nv_bfloat16* src = buf ? g_VTlo : g_VThi;
        #pragma unroll
        for (int i = 0; i < 4; ++i) {
            int fi = tid + i * THREADS;        // kb(1)|d(6)|c8(3)
            int kb = fi >> 9, d = (fi >> 3) & 63, c8 = fi & 7;
            uint4 u = *reinterpret_cast<const uint4*>(
                src + ((size_t)bh * Dh + d) * S + t0 + kb * 64 + c8 * 8);
            *reinterpret_cast<uint4*>(sm + OFF_V + buf * 16384 + kb * 8192 +
                                      swz((uint32_t)(d * 128 + c8 * 16))) = u;
        }
    }
}

// scores c[16 nblk][4] = Q(warp rows) x K_tile^T, 3-term bf16
__device__ __forceinline__ void qk_tile(uint32_t sb, const uint32_t qa[2][4][4],
                                        int lane, float (&c)[16][4]) {
    #pragma unroll
    for (int nb = 0; nb < 16; ++nb)
        #pragma unroll
        for (int e = 0; e < 4; ++e) c[nb][e] = 0.f;
    #pragma unroll
    for (int nb2 = 0; nb2 < 8; ++nb2) {
        #pragma unroll
        for (int ks = 0; ks < 4; ++ks) {
            uint32_t rowb = nb2 * 16 + (lane & 15);
            uint32_t colb = ks * 32 + ((lane >> 4) & 1) * 16;
            uint32_t ah = sb + OFF_K + swz(rowb * 128 + colb);
            uint32_t kh[4], kl[4];
            LDSM4(kh, ah);
            LDSM4(kl, ah + 16384);
            // nblock0 B = {r0,r2}; nblock1 B = {r1,r3}
            mma_bf16(c[nb2 * 2],     qa[0][ks], kh[0], kh[2]);
            mma_bf16(c[nb2 * 2],     qa[0][ks], kl[0], kl[2]);
            mma_bf16(c[nb2 * 2],     qa[1][ks], kh[0], kh[2]);
            mma_bf16(c[nb2 * 2 + 1], qa[0][ks], kh[1], kh[3]);
            mma_bf16(c[nb2 * 2 + 1], qa[0][ks], kl[1], kl[3]);
            mma_bf16(c[nb2 * 2 + 1], qa[1][ks], kh[1], kh[3]);
        }
    }
}
}  // namespace

__global__ __launch_bounds__(THREADS, 1)
void attn_main(const int* __restrict__ mask, float* __restrict__ out,
               float* __restrict__ p_attn)
{
    extern __shared__ char sm[];
    const uint32_t sb = s2u(sm);
    const int tid = threadIdx.x;
    const int w = tid >> 5, lane = tid & 31;
    const int qt = blockIdx.x, bh = blockIdx.y;
    const int b = bh >> 4;                 // H = 16
    const int q0 = qt * MQ;
    float* msf  = reinterpret_cast<float*>(sm + OFF_MS);
    float* sinv = reinterpret_cast<float*>(sm + OFF_INV);

    // ---- Q tile into smem (bf16 hi/lo, swizzled) ----
    #pragma unroll
    for (int buf = 0; buf < 2; ++buf) {
        const __nv_bfloat16* src = buf ? g_Qlo : g_Qhi;
        #pragma unroll
        for (int i = 0; i < 4; ++i) {
            int fi = tid + i * THREADS;
            int row = fi >> 3, c8 = fi & 7;
            uint4 u = *reinterpret_cast<const uint4*>(
                src + ((size_t)bh * S + q0 + row) * Dh + c8 * 8);
            *reinterpret_cast<uint4*>(sm + OFF_Q + buf * 16384 +
                                      swz((uint32_t)(row * 128 + c8 * 16))) = u;
        }
    }
    for (int i = tid; i < S; i += THREADS)
        msf[i] = (mask[b * S + i] != 0) ? 1.0f : 0.0f;
    __syncthreads();

    // ---- preload Q A-fragments (warp's 16 m-rows) ----
    uint32_t qa[2][4][4];
    #pragma unroll
    for (int buf = 0; buf < 2; ++buf)
        #pragma unroll
        for (int ks = 0; ks < 4; ++ks) {
            uint32_t a = sb + OFF_Q + buf * 16384 +
                swz((uint32_t)((w * 16 + (lane & 15)) * 128 + ks * 32 +
                               ((lane >> 4) & 1) * 16));
            LDSM4(qa[buf][ks], a);
        }

    // ================== PASS A: rowsums ==================
    float rs0 = 0.f, rs1 = 0.f;
    for (int t = 0; t < NT; ++t) {
        const int t0 = t * NK;
        __syncthreads();
        load_k_tile(sm, tid, bh, t0);
        __syncthreads();
        float c[16][4];
        qk_tile(sb, qa, lane, c);
        #pragma unroll
        for (int nb = 0; nb < 16; ++nb) {
            int col = t0 + nb * 8 + 2 * (lane & 3);
            float m0 = msf[col], m1 = msf[col + 1];
            rs0 += m0 * __expf(c[nb][0]) + m1 * __expf(c[nb][1]);
            rs1 += m0 * __expf(c[nb][2]) + m1 * __expf(c[nb][3]);
        }
    }
    rs0 += __shfl_xor_sync(0xffffffffu, rs0, 1);
    rs0 += __shfl_xor_sync(0xffffffffu, rs0, 2);
    rs1 += __shfl_xor_sync(0xffffffffu, rs1, 1);
    rs1 += __shfl_xor_sync(0xffffffffu, rs1, 2);
    if ((lane & 3) == 0) {
        sinv[w * 16 + (lane >> 2)]     = 1.0f / rs0;
        sinv[w * 16 + 8 + (lane >> 2)] = 1.0f / rs1;
    }
    __syncthreads();
    const float inv0 = sinv[w * 16 + (lane >> 2)];
    const float inv1 = sinv[w * 16 + 8 + (lane >> 2)];

    // ================== PASS B: p_attn + out ==================
    float oacc[8][4];
    #pragma unroll
    for (int d = 0; d < 8; ++d)
        #pragma unroll
        for (int e = 0; e < 4; ++e) oacc[d][e] = 0.f;

    const int r0g = q0 + w * 16 + (lane >> 2);
    const uint32_t pw = OFF_P + w * 8192;

    for (int t = 0; t < NT; ++t) {
        const int t0 = t * NK;
        __syncthreads();
        load_k_tile(sm, tid, bh, t0);
        load_v_tile(sm, tid, bh, t0);
        __syncthreads();
        float c[16][4];
        qk_tile(sb, qa, lane, c);

        // epilogue: p = mask*exp(score)*inv → p_attn global + P smem (bf16 hi/lo)
        #pragma unroll
        for (int nb = 0; nb < 16; ++nb) {
            int cb = nb * 8 + 2 * (lane & 3);
            int col = t0 + cb;
            float m0 = msf[col], m1 = msf[col + 1];
            float p00 = m0 * __expf(c[nb][0]) * inv0;
            float p01 = m1 * __expf(c[nb][1]) * inv0;
            float p10 = m0 * __expf(c[nb][2]) * inv1;
            float p11 = m1 * __expf(c[nb][3]) * inv1;
            float2 w0 = make_float2(p00, p01);
            float2 w1 = make_float2(p10, p11);
            *reinterpret_cast<float2*>(p_attn + ((size_t)bh * S + r0g) * S + col) = w0;
            *reinterpret_cast<float2*>(p_attn + ((size_t)bh * S + r0g + 8) * S + col) = w1;
            int kb = cb >> 6, kc = cb & 63;
            uint32_t o0 = kb * 2048 + swz((uint32_t)((lane >> 2) * 128 + kc * 2));
            uint32_t o1 = kb * 2048 + swz((uint32_t)(((lane >> 2) + 8) * 128 + kc * 2));
            *reinterpret_cast<uint32_t*>(sm + pw + o0)        = pack_hi(p00, p01);
            *reinterpret_cast<uint32_t*>(sm + pw + o1)        = pack_hi(p10, p11);
            *reinterpret_cast<uint32_t*>(sm + pw + 4096 + o0) = pack_lo(p00, p01);
            *reinterpret_cast<uint32_t*>(sm + pw + 4096 + o1) = pack_lo(p10, p11);
        }
        __syncwarp();

        // PV: oacc += P(16x128) * V^T(64x128)^T  (3-term)
        #pragma unroll
        for (int ksp = 0; ksp < 8; ++ksp) {
            int kb = ksp >> 2;
            uint32_t kcb = (ksp & 3) * 32 + ((lane >> 4) & 1) * 16;
            uint32_t aaddr = sb + pw + kb * 2048 + swz((uint32_t)((lane & 15) * 128) + kcb);
            uint32_t pa_h[4], pa_l[4];
            LDSM4(pa_h, aaddr);
            LDSM4(pa_l, aaddr + 4096);
            #pragma unroll
            for (int db2 = 0; db2 < 4; ++db2) {
                uint32_t vaddr = sb + OFF_V + kb * 8192 +
                    swz((uint32_t)((db2 * 16 + (lane & 15)) * 128) + kcb);
                uint32_t vh[4], vl[4];
                LDSM4(vh, vaddr);
                LDSM4(vl, vaddr + 16384);
                mma_bf16(oacc[db2 * 2],     pa_h, vh[0], vh[2]);
                mma_bf16(oacc[db2 * 2],     pa_h, vl[0], vl[2]);
                mma_bf16(oacc[db2 * 2],     pa_l, vh[0], vh[2]);
                mma_bf16(oacc[db2 * 2 + 1], pa_h, vh[1], vh[3]);
                mma_bf16(oacc[db2 * 2 + 1], pa_h, vl[1], vl[3]);
                mma_bf16(oacc[db2 * 2 + 1], pa_l, vh[1], vh[3]);
            }
        }
    }

    // ---- out store ----
    #pragma unroll
    for (int db = 0; db < 8; ++db) {
        int col = db * 8 + 2 * (lane & 3);
        float2 w0 = make_float2(oacc[db][0], oacc[db][1]);
        float2 w1 = make_float2(oacc[db][2], oacc[db][3]);
        *reinterpret_cast<float2*>(out + ((size_t)bh * S + r0g) * Dh + col) = w0;
        *reinterpret_cast<float2*>(out + ((size_t)bh * S + r0g + 8) * Dh + col) = w1;
    }
}

extern "C" void kernel_launch(void* const* d_in, const int* in_sizes, int n_in,
                              void* d_out, int out_size) {
    const float* q = (const float*)d_in[0];
    const float* k = (const float*)d_in[1];
    const float* v = (const float*)d_in[2];
    const int* mask = (const int*)d_in[3];

    float* out = (float*)d_out;
    float* p_attn = out + (size_t)Bn * Hn * S * Dh;

    conv_qk<<<NELEM / 4 / THREADS, THREADS>>>(q, k);
    conv_vt<<<dim3(S / 32, Dh / 32, BH), dim3(32, 8)>>>(v);

    cudaFuncSetAttribute(attn_main, cudaFuncAttributeMaxDynamicSharedMemorySize, SMEM_BYTES);
    attn_main<<<dim3(S / MQ, BH), THREADS, SMEM_BYTES>>>(mask, out, p_attn);
}

// round 4
// speedup vs baseline: 3.2296x; 1.4497x over previous
#include <cuda_runtime.h>
#include <cuda_bf16.h>
#include <cstdint>

namespace {
constexpr int Bn = 4, Hn = 16, S = 2048, Dh = 64;
constexpr int BH = Bn * Hn;
constexpr int MQ = 128;
constexpr int NK = 128;
constexpr int NT = S / NK;
constexpr int THREADS = 256;
constexpr int NELEM = BH * S * Dh;

// smem layout: Q (prologue) aliases V (pass B)
constexpr int OFF_QV  = 0;              // [2 hi/lo][...] 32768 B
constexpr int OFF_K   = 32768;          // [2 hi/lo][128][64] bf16 = 32768 B
constexpr int OFF_MS  = 65536;          // 2048 f32 = 8192 B
constexpr int OFF_INV = 73728;          // 128 f32
constexpr unsigned SMEM_BYTES = OFF_INV + 512;   // 74,240 B -> 2 CTAs/SM
}

__device__ __nv_bfloat16 g_Qhi[NELEM], g_Qlo[NELEM];
__device__ __nv_bfloat16 g_Khi[NELEM], g_Klo[NELEM];
__device__ __nv_bfloat16 g_VThi[NELEM], g_VTlo[NELEM];   // [bh][d][s]

__device__ __forceinline__ uint32_t s2u(const void* p) {
    uint32_t a;
    asm("{ .reg .u64 t; cvta.to.shared.u64 t, %1; cvt.u32.u64 %0, t; }" : "=r"(a) : "l"(p));
    return a;
}
__device__ __forceinline__ uint32_t swz(uint32_t o) { return o ^ ((o >> 3) & 0x70); }

#define LDSM4(r, a) \
    asm volatile("ldmatrix.sync.aligned.m8n8.x4.shared.b16 {%0,%1,%2,%3},[%4];" \
                 : "=r"((r)[0]), "=r"((r)[1]), "=r"((r)[2]), "=r"((r)[3]) : "r"(a))
#define CP16(dst, src) \
    asm volatile("cp.async.cg.shared.global [%0], [%1], 16;" :: "r"(dst), "l"(src))
#define CP_COMMIT() asm volatile("cp.async.commit_group;" ::: "memory")
#define CP_WAIT()   asm volatile("cp.async.wait_all;" ::: "memory")

__device__ __forceinline__ void mma_bf16(float c[4], const uint32_t a[4],
                                         uint32_t b0, uint32_t b1) {
    asm volatile(
        "mma.sync.aligned.m16n8k16.row.col.f32.bf16.bf16.f32 "
        "{%0,%1,%2,%3},{%4,%5,%6,%7},{%8,%9},{%0,%1,%2,%3};"
        : "+f"(c[0]), "+f"(c[1]), "+f"(c[2]), "+f"(c[3])
        : "r"(a[0]), "r"(a[1]), "r"(a[2]), "r"(a[3]), "r"(b0), "r"(b1));
}

__device__ __forceinline__ void fsplit(float x, __nv_bfloat16& h, __nv_bfloat16& l) {
    h = __float2bfloat16_rn(x);
    l = __float2bfloat16_rn(x - __bfloat162float(h));
}
__device__ __forceinline__ uint32_t pack_hi(float x, float y) {
    __nv_bfloat162 t;
    t.x = __float2bfloat16_rn(x);
    t.y = __float2bfloat16_rn(y);
    return *reinterpret_cast<uint32_t*>(&t);
}
__device__ __forceinline__ uint32_t pack_lo(float x, float y) {
    __nv_bfloat162 t;
    t.x = __float2bfloat16_rn(x - __bfloat162float(__float2bfloat16_rn(x)));
    t.y = __float2bfloat16_rn(y - __bfloat162float(__float2bfloat16_rn(y)));
    return *reinterpret_cast<uint32_t*>(&t);
}

// ---------------- pre-kernels ----------------
__global__ void conv_qk(const float* __restrict__ q, const float* __restrict__ k) {
    size_t i4 = (size_t)blockIdx.x * blockDim.x + threadIdx.x;
    size_t e = i4 * 4;
    float4 qv = *reinterpret_cast<const float4*>(q + e);
    float4 kv = *reinterpret_cast<const float4*>(k + e);
    qv.x *= 0.125f; qv.y *= 0.125f; qv.z *= 0.125f; qv.w *= 0.125f;
    uint2 w;
    w.x = pack_hi(qv.x, qv.y); w.y = pack_hi(qv.z, qv.w);
    *reinterpret_cast<uint2*>(g_Qhi + e) = w;
    w.x = pack_lo(qv.x, qv.y); w.y = pack_lo(qv.z, qv.w);
    *reinterpret_cast<uint2*>(g_Qlo + e) = w;
    w.x = pack_hi(kv.x, kv.y); w.y = pack_hi(kv.z, kv.w);
    *reinterpret_cast<uint2*>(g_Khi + e) = w;
    w.x = pack_lo(kv.x, kv.y); w.y = pack_lo(kv.z, kv.w);
    *reinterpret_cast<uint2*>(g_Klo + e) = w;
}

__global__ void conv_vt(const float* __restrict__ v) {
    __shared__ float t[32][33];
    const int bh = blockIdx.z, s0 = blockIdx.x * 32, d0 = blockIdx.y * 32;
    const int tx = threadIdx.x, ty = threadIdx.y;   // (32, 8)
    #pragma unroll
    for (int j = 0; j < 4; ++j)
        t[ty + 8 * j][tx] = v[((size_t)bh * S + s0 + ty + 8 * j) * Dh + d0 + tx];
    __syncthreads();
    #pragma unroll
    for (int j = 0; j < 4; ++j) {
        float x = t[tx][ty + 8 * j];
        __nv_bfloat16 h, l;
        fsplit(x, h, l);
        size_t o = ((size_t)bh * Dh + d0 + ty + 8 * j) * S + s0 + tx;
        g_VThi[o] = h; g_VTlo[o] = l;
    }
}

// ---------------- main kernel ----------------
__global__ __launch_bounds__(THREADS, 2)
void attn_main(const int* __restrict__ mask, float* __restrict__ out,
               float* __restrict__ p_attn)
{
    extern __shared__ char sm[];
    const uint32_t sb = s2u(sm);
    const int tid = threadIdx.x;
    const int w = tid >> 5, lane = tid & 31;
    const int qt = blockIdx.x, bh = blockIdx.y;
    const int b = bh >> 4;
    const int q0 = qt * MQ;
    float* msf  = reinterpret_cast<float*>(sm + OFF_MS);
    float* sinv = reinterpret_cast<float*>(sm + OFF_INV);

    // ---- prologue: Q (hi/lo) via cp.async + mask ----
    #pragma unroll
    for (int buf = 0; buf < 2; ++buf) {
        const __nv_bfloat16* src = buf ? g_Qlo : g_Qhi;
        #pragma unroll
        for (int i = 0; i < 4; ++i) {
            int fi = tid + i * THREADS;
            int row = fi >> 3, c8 = fi & 7;
            CP16(sb + OFF_QV + buf * 16384 + swz((uint32_t)(row * 128 + c8 * 16)),
                 src + ((size_t)bh * S + q0 + row) * Dh + c8 * 8);
        }
    }
    for (int i = tid; i < S; i += THREADS)
        msf[i] = (mask[b * S + i] != 0) ? 1.0f : 0.0f;
    CP_COMMIT(); CP_WAIT();
    __syncthreads();

    // ---- Q fragments (persistent registers) ----
    uint32_t qa[2][4][4];
    #pragma unroll
    for (int buf = 0; buf < 2; ++buf)
        #pragma unroll
        for (int ks = 0; ks < 4; ++ks) {
            uint32_t a = sb + OFF_QV + buf * 16384 +
                swz((uint32_t)((w * 16 + (lane & 15)) * 128 + ks * 32 +
                               ((lane >> 4) & 1) * 16));
            LDSM4(qa[buf][ks], a);
        }

    // ================== PASS A: rowsums (2-term QK, K-hi only) ==================
    float rs0 = 0.f, rs1 = 0.f;
    for (int t = 0; t < NT; ++t) {
        const int t0 = t * NK;
        __syncthreads();
        #pragma unroll
        for (int i = 0; i < 4; ++i) {
            int fi = tid + i * THREADS;
            int row = fi >> 3, c8 = fi & 7;
            CP16(sb + OFF_K + swz((uint32_t)(row * 128 + c8 * 16)),
                 g_Khi + ((size_t)bh * S + t0 + row) * Dh + c8 * 8);
        }
        CP_COMMIT(); CP_WAIT();
        __syncthreads();
        #pragma unroll
        for (int half = 0; half < 2; ++half) {
            float c[8][4];
            #pragma unroll
            for (int nb = 0; nb < 8; ++nb)
                #pragma unroll
                for (int e = 0; e < 4; ++e) c[nb][e] = 0.f;
            #pragma unroll
            for (int nb2 = 0; nb2 < 4; ++nb2) {
                uint32_t rowb = half * 64 + nb2 * 16 + (lane & 15);
                #pragma unroll
                for (int ks = 0; ks < 4; ++ks) {
                    uint32_t kh[4];
                    LDSM4(kh, sb + OFF_K + swz(rowb * 128 + ks * 32 +
                                               ((lane >> 4) & 1) * 16));
                    mma_bf16(c[nb2 * 2],     qa[0][ks], kh[0], kh[2]);
                    mma_bf16(c[nb2 * 2],     qa[1][ks], kh[0], kh[2]);
                    mma_bf16(c[nb2 * 2 + 1], qa[0][ks], kh[1], kh[3]);
                    mma_bf16(c[nb2 * 2 + 1], qa[1][ks], kh[1], kh[3]);
                }
            }
            #pragma unroll
            for (int nb = 0; nb < 8; ++nb) {
                int col = t0 + half * 64 + nb * 8 + 2 * (lane & 3);
                float m0 = msf[col], m1 = msf[col + 1];
                rs0 += m0 * __expf(c[nb][0]) + m1 * __expf(c[nb][1]);
                rs1 += m0 * __expf(c[nb][2]) + m1 * __expf(c[nb][3]);
            }
        }
    }
    rs0 += __shfl_xor_sync(0xffffffffu, rs0, 1);
    rs0 += __shfl_xor_sync(0xffffffffu, rs0, 2);
    rs1 += __shfl_xor_sync(0xffffffffu, rs1, 1);
    rs1 += __shfl_xor_sync(0xffffffffu, rs1, 2);
    if ((lane & 3) == 0) {
        sinv[w * 16 + (lane >> 2)]     = 1.0f / rs0;
        sinv[w * 16 + 8 + (lane >> 2)] = 1.0f / rs1;
    }
    __syncthreads();
    const float inv0 = sinv[w * 16 + (lane >> 2)];
    const float inv1 = sinv[w * 16 + 8 + (lane >> 2)];

    // ================== PASS B: 3-term QK + register-direct PV ==================
    float oacc[8][4];
    #pragma unroll
    for (int d = 0; d < 8; ++d)
        #pragma unroll
        for (int e = 0; e < 4; ++e) oacc[d][e] = 0.f;

    const int r0g = q0 + w * 16 + (lane >> 2);

    for (int t = 0; t < NT; ++t) {
        const int t0 = t * NK;
        __syncthreads();
        #pragma unroll
        for (int buf = 0; buf < 2; ++buf) {
            const __nv_bfloat16* ksrc = buf ? g_Klo : g_Khi;
            const __nv_bfloat16* vsrc = buf ? g_VTlo : g_VThi;
            #pragma unroll
            for (int i = 0; i < 4; ++i) {
                int fi = tid + i * THREADS;
                int row = fi >> 3, c8 = fi & 7;
                CP16(sb + OFF_K + buf * 16384 + swz((uint32_t)(row * 128 + c8 * 16)),
                     ksrc + ((size_t)bh * S + t0 + row) * Dh + c8 * 8);
                int kb = fi >> 9, d = (fi >> 3) & 63;
                CP16(sb + OFF_QV + buf * 16384 + kb * 8192 +
                         swz((uint32_t)(d * 128 + c8 * 16)),
                     vsrc + ((size_t)bh * Dh + d) * S + t0 + kb * 64 + c8 * 8);
            }
        }
        CP_COMMIT(); CP_WAIT();
        __syncthreads();

        #pragma unroll
        for (int half = 0; half < 2; ++half) {
            float c[8][4];
            #pragma unroll
            for (int nb = 0; nb < 8; ++nb)
                #pragma unroll
                for (int e = 0; e < 4; ++e) c[nb][e] = 0.f;
            #pragma unroll
            for (int nb2 = 0; nb2 < 4; ++nb2) {
                uint32_t rowb = half * 64 + nb2 * 16 + (lane & 15);
                #pragma unroll
                for (int ks = 0; ks < 4; ++ks) {
                    uint32_t ah2 = sb + OFF_K + swz(rowb * 128 + ks * 32 +
                                                    ((lane >> 4) & 1) * 16);
                    uint32_t kh[4], kl[4];
                    LDSM4(kh, ah2);
                    LDSM4(kl, ah2 + 16384);
                    mma_bf16(c[nb2 * 2],     qa[0][ks], kh[0], kh[2]);
                    mma_bf16(c[nb2 * 2],     qa[0][ks], kl[0], kl[2]);
                    mma_bf16(c[nb2 * 2],     qa[1][ks], kh[0], kh[2]);
                    mma_bf16(c[nb2 * 2 + 1], qa[0][ks], kh[1], kh[3]);
                    mma_bf16(c[nb2 * 2 + 1], qa[0][ks], kl[1], kl[3]);
                    mma_bf16(c[nb2 * 2 + 1], qa[1][ks], kh[1], kh[3]);
                }
            }
            // epilogue: p = mask*exp*inv -> p_attn global + A fragments in regs
            uint32_t ah[4][4], al[4][4];
            #pragma unroll
            for (int nb = 0; nb < 8; ++nb) {
                int cb = half * 64 + nb * 8 + 2 * (lane & 3);
                int col = t0 + cb;
                float m0 = msf[col], m1 = msf[col + 1];
                float p00 = m0 * __expf(c[nb][0]) * inv0;
                float p01 = m1 * __expf(c[nb][1]) * inv0;
                float p10 = m0 * __expf(c[nb][2]) * inv1;
                float p11 = m1 * __expf(c[nb][3]) * inv1;
                *reinterpret_cast<float2*>(p_attn + ((size_t)bh * S + r0g) * S + col) =
                    make_float2(p00, p01);
                *reinterpret_cast<float2*>(p_attn + ((size_t)bh * S + r0g + 8) * S + col) =
                    make_float2(p10, p11);
                int ks16 = nb >> 1, h8 = (nb & 1) * 2;
                ah[ks16][h8 + 0] = pack_hi(p00, p01);
                ah[ks16][h8 + 1] = pack_hi(p10, p11);
                al[ks16][h8 + 0] = pack_lo(p00, p01);
                al[ks16][h8 + 1] = pack_lo(p10, p11);
            }
            // PV over this half's 64 keys (kb block = half)
            #pragma unroll
            for (int ks16 = 0; ks16 < 4; ++ks16) {
                uint32_t kcb = ks16 * 32 + ((lane >> 4) & 1) * 16;
                #pragma unroll
                for (int db2 = 0; db2 < 4; ++db2) {
                    uint32_t vaddr = sb + OFF_QV + half * 8192 +
                        swz((uint32_t)((db2 * 16 + (lane & 15)) * 128) + kcb);
                    uint32_t vh[4], vl[4];
                    LDSM4(vh, vaddr);
                    LDSM4(vl, vaddr + 16384);
                    mma_bf16(oacc[db2 * 2],     ah[ks16], vh[0], vh[2]);
                    mma_bf16(oacc[db2 * 2],     ah[ks16], vl[0], vl[2]);
                    mma_bf16(oacc[db2 * 2],     al[ks16], vh[0], vh[2]);
                    mma_bf16(oacc[db2 * 2 + 1], ah[ks16], vh[1], vh[3]);
                    mma_bf16(oacc[db2 * 2 + 1], ah[ks16], vl[1], vl[3]);
                    mma_bf16(oacc[db2 * 2 + 1], al[ks16], vh[1], vh[3]);
                }
            }
        }
    }

    // ---- out store ----
    #pragma unroll
    for (int db = 0; db < 8; ++db) {
        int col = db * 8 + 2 * (lane & 3);
        *reinterpret_cast<float2*>(out + ((size_t)bh * S + r0g) * Dh + col) =
            make_float2(oacc[db][0], oacc[db][1]);
        *reinterpret_cast<float2*>(out + ((size_t)bh * S + r0g + 8) * Dh + col) =
            make_float2(oacc[db][2], oacc[db][3]);
    }
}

extern "C" void kernel_launch(void* const* d_in, const int* in_sizes, int n_in,
                              void* d_out, int out_size) {
    const float* q = (const float*)d_in[0];
    const float* k = (const float*)d_in[1];
    const float* v = (const float*)d_in[2];
    const int* mask = (const int*)d_in[3];

    float* out = (float*)d_out;
    float* p_attn = out + (size_t)Bn * Hn * S * Dh;

    conv_qk<<<NELEM / 4 / THREADS, THREADS>>>(q, k);
    conv_vt<<<dim3(S / 32, Dh / 32, BH), dim3(32, 8)>>>(v);

    cudaFuncSetAttribute(attn_main, cudaFuncAttributeMaxDynamicSharedMemorySize, SMEM_BYTES);
    attn_main<<<dim3(S / MQ, BH), THREADS, SMEM_BYTES>>>(mask, out, p_attn);
}

// round 5
// speedup vs baseline: 3.4823x; 1.0783x over previous
#include <cuda_runtime.h>
#include <cuda_bf16.h>
#include <cstdint>

namespace {
constexpr int Bn = 4, Hn = 16, S = 2048, Dh = 64;
constexpr int BH = Bn * Hn;
constexpr int MQ = 128;
constexpr int NK = 64;            // keys per tile (double-buffered)
constexpr int NT = S / NK;        // 32
constexpr int THREADS = 256;
constexpr int NELEM = BH * S * Dh;

// smem: K buffers [2 buf][2 hilo][64][128B] = 32KB ; V same = 32KB
// prologue reuses [0,32KB) for Q hi/lo; pass A uses K region as [2 buf][8KB] hi-only
constexpr int OFF_K   = 0;
constexpr int OFF_V   = 32768;
constexpr int OFF_MS  = 65536;          // 2048 f32
constexpr int OFF_INV = 73728;          // 128 f32
constexpr unsigned SMEM_BYTES = OFF_INV + 512;   // 74,240 B -> 2 CTAs/SM
}

__device__ __nv_bfloat16 g_Qhi[NELEM], g_Qlo[NELEM];
__device__ __nv_bfloat16 g_Khi[NELEM], g_Klo[NELEM];
__device__ __nv_bfloat16 g_VThi[NELEM], g_VTlo[NELEM];   // [bh][d][s]

__device__ __forceinline__ uint32_t s2u(const void* p) {
    uint32_t a;
    asm("{ .reg .u64 t; cvta.to.shared.u64 t, %1; cvt.u32.u64 %0, t; }" : "=r"(a) : "l"(p));
    return a;
}
__device__ __forceinline__ uint32_t swz(uint32_t o) { return o ^ ((o >> 3) & 0x70); }

#define LDSM4(r, a) \
    asm volatile("ldmatrix.sync.aligned.m8n8.x4.shared.b16 {%0,%1,%2,%3},[%4];" \
                 : "=r"((r)[0]), "=r"((r)[1]), "=r"((r)[2]), "=r"((r)[3]) : "r"(a))
#define CP16(dst, src) \
    asm volatile("cp.async.cg.shared.global [%0], [%1], 16;" :: "r"(dst), "l"(src))
#define CP_COMMIT() asm volatile("cp.async.commit_group;" ::: "memory")
#define CP_WAIT0()  asm volatile("cp.async.wait_group 0;" ::: "memory")
#define CP_WAIT1()  asm volatile("cp.async.wait_group 1;" ::: "memory")

__device__ __forceinline__ void mma_bf16(float c[4], const uint32_t a[4],
                                         uint32_t b0, uint32_t b1) {
    asm volatile(
        "mma.sync.aligned.m16n8k16.row.col.f32.bf16.bf16.f32 "
        "{%0,%1,%2,%3},{%4,%5,%6,%7},{%8,%9},{%0,%1,%2,%3};"
        : "+f"(c[0]), "+f"(c[1]), "+f"(c[2]), "+f"(c[3])
        : "r"(a[0]), "r"(a[1]), "r"(a[2]), "r"(a[3]), "r"(b0), "r"(b1));
}

__device__ __forceinline__ void fsplit(float x, __nv_bfloat16& h, __nv_bfloat16& l) {
    h = __float2bfloat16_rn(x);
    l = __float2bfloat16_rn(x - __bfloat162float(h));
}
__device__ __forceinline__ uint32_t pack_hi(float x, float y) {
    __nv_bfloat162 t;
    t.x = __float2bfloat16_rn(x);
    t.y = __float2bfloat16_rn(y);
    return *reinterpret_cast<uint32_t*>(&t);
}
__device__ __forceinline__ uint32_t pack_lo(float x, float y) {
    __nv_bfloat162 t;
    t.x = __float2bfloat16_rn(x - __bfloat162float(__float2bfloat16_rn(x)));
    t.y = __float2bfloat16_rn(y - __bfloat162float(__float2bfloat16_rn(y)));
    return *reinterpret_cast<uint32_t*>(&t);
}
// fused: hi + residual-lo packing (hi conversion reused)
__device__ __forceinline__ void pack_hilo(float x, float y, uint32_t& hi, uint32_t& lo) {
    __nv_bfloat162 h, l;
    h.x = __float2bfloat16_rn(x);
    h.y = __float2bfloat16_rn(y);
    l.x = __float2bfloat16_rn(x - __bfloat162float(h.x));
    l.y = __float2bfloat16_rn(y - __bfloat162float(h.y));
    hi = *reinterpret_cast<uint32_t*>(&h);
    lo = *reinterpret_cast<uint32_t*>(&l);
}

// ---------------- pre-kernels ----------------
__global__ void conv_qk(const float* __restrict__ q, const float* __restrict__ k) {
    size_t i4 = (size_t)blockIdx.x * blockDim.x + threadIdx.x;
    size_t e = i4 * 4;
    float4 qv = *reinterpret_cast<const float4*>(q + e);
    float4 kv = *reinterpret_cast<const float4*>(k + e);
    qv.x *= 0.125f; qv.y *= 0.125f; qv.z *= 0.125f; qv.w *= 0.125f;
    uint2 w;
    w.x = pack_hi(qv.x, qv.y); w.y = pack_hi(qv.z, qv.w);
    *reinterpret_cast<uint2*>(g_Qhi + e) = w;
    w.x = pack_lo(qv.x, qv.y); w.y = pack_lo(qv.z, qv.w);
    *reinterpret_cast<uint2*>(g_Qlo + e) = w;
    w.x = pack_hi(kv.x, kv.y); w.y = pack_hi(kv.z, kv.w);
    *reinterpret_cast<uint2*>(g_Khi + e) = w;
    w.x = pack_lo(kv.x, kv.y); w.y = pack_lo(kv.z, kv.w);
    *reinterpret_cast<uint2*>(g_Klo + e) = w;
}

__global__ void conv_vt(const float* __restrict__ v) {
    __shared__ float t[32][33];
    const int bh = blockIdx.z, s0 = blockIdx.x * 32, d0 = blockIdx.y * 32;
    const int tx = threadIdx.x, ty = threadIdx.y;   // (32, 8)
    #pragma unroll
    for (int j = 0; j < 4; ++j)
        t[ty + 8 * j][tx] = v[((size_t)bh * S + s0 + ty + 8 * j) * Dh + d0 + tx];
    __syncthreads();
    #pragma unroll
    for (int j = 0; j < 4; ++j) {
        float x = t[tx][ty + 8 * j];
        __nv_bfloat16 h, l;
        fsplit(x, h, l);
        size_t o = ((size_t)bh * Dh + d0 + ty + 8 * j) * S + s0 + tx;
        g_VThi[o] = h; g_VTlo[o] = l;
    }
}

// ---------------- main kernel ----------------
__global__ __launch_bounds__(THREADS, 2)
void attn_main(const int* __restrict__ mask, float* __restrict__ out,
               float* __restrict__ p_attn)
{
    extern __shared__ char sm[];
    const uint32_t sb = s2u(sm);
    const int tid = threadIdx.x;
    const int w = tid >> 5, lane = tid & 31;
    const int qt = blockIdx.x, bh = blockIdx.y;
    const int b = bh >> 4;
    const int q0 = qt * MQ;
    float* msf  = reinterpret_cast<float*>(sm + OFF_MS);
    float* sinv = reinterpret_cast<float*>(sm + OFF_INV);

    // ---- prologue: Q (hi/lo) into [0,32KB) + mask ----
    #pragma unroll
    for (int buf = 0; buf < 2; ++buf) {
        const __nv_bfloat16* src = buf ? g_Qlo : g_Qhi;
        #pragma unroll
        for (int i = 0; i < 4; ++i) {
            int fi = tid + i * THREADS;
            int row = fi >> 3, c8 = fi & 7;
            CP16(sb + buf * 16384 + swz((uint32_t)(row * 128 + c8 * 16)),
                 src + ((size_t)bh * S + q0 + row) * Dh + c8 * 8);
        }
    }
    for (int i = tid; i < S; i += THREADS)
        msf[i] = (mask[b * S + i] != 0) ? 1.0f : 0.0f;
    CP_COMMIT(); CP_WAIT0();
    __syncthreads();

    // ---- Q fragments (persistent registers) ----
    uint32_t qa[2][4][4];
    #pragma unroll
    for (int buf = 0; buf < 2; ++buf)
        #pragma unroll
        for (int ks = 0; ks < 4; ++ks) {
            uint32_t a = sb + buf * 16384 +
                swz((uint32_t)((w * 16 + (lane & 15)) * 128 + ks * 32 +
                               ((lane >> 4) & 1) * 16));
            LDSM4(qa[buf][ks], a);
        }
    __syncthreads();   // Q smem free for reuse

    // ================== PASS A: rowsums (1-term QK, hi only, dbl-buffered) ==================
    // K-hi tile: 64 rows x 128B = 8KB at OFF_K + buf*8192
    float rs0 = 0.f, rs1 = 0.f;
    {
        // preload tile 0
        #pragma unroll
        for (int i = 0; i < 2; ++i) {
            int fi = tid + i * THREADS;
            int row = fi >> 3, c8 = fi & 7;
            CP16(sb + OFF_K + swz((uint32_t)(row * 128 + c8 * 16)),
                 g_Khi + ((size_t)bh * S + row) * Dh + c8 * 8);
        }
        CP_COMMIT();
        for (int t = 0; t < NT; ++t) {
            const int t0 = t * NK;
            if (t + 1 < NT) {
                const uint32_t dstb = sb + OFF_K + ((t + 1) & 1) * 8192;
                #pragma unroll
                for (int i = 0; i < 2; ++i) {
                    int fi = tid + i * THREADS;
                    int row = fi >> 3, c8 = fi & 7;
                    CP16(dstb + swz((uint32_t)(row * 128 + c8 * 16)),
                         g_Khi + ((size_t)bh * S + t0 + NK + row) * Dh + c8 * 8);
                }
                CP_COMMIT(); CP_WAIT1();
            } else {
                CP_WAIT0();
            }
            __syncthreads();
            const uint32_t kbase = sb + OFF_K + (t & 1) * 8192;
            float c[8][4];
            #pragma unroll
            for (int nb = 0; nb < 8; ++nb)
                #pragma unroll
                for (int e = 0; e < 4; ++e) c[nb][e] = 0.f;
            #pragma unroll
            for (int nb2 = 0; nb2 < 4; ++nb2) {
                uint32_t rowb = nb2 * 16 + (lane & 15);
                #pragma unroll
                for (int ks = 0; ks < 4; ++ks) {
                    uint32_t kh[4];
                    LDSM4(kh, kbase + swz(rowb * 128 + ks * 32 +
                                          ((lane >> 4) & 1) * 16));
                    mma_bf16(c[nb2 * 2],     qa[0][ks], kh[0], kh[2]);
                    mma_bf16(c[nb2 * 2 + 1], qa[0][ks], kh[1], kh[3]);
                }
            }
            #pragma unroll
            for (int nb = 0; nb < 8; ++nb) {
                int col = t0 + nb * 8 + 2 * (lane & 3);
                float m0 = msf[col], m1 = msf[col + 1];
                rs0 += m0 * __expf(c[nb][0]) + m1 * __expf(c[nb][1]);
                rs1 += m0 * __expf(c[nb][2]) + m1 * __expf(c[nb][3]);
            }
            __syncthreads();
        }
    }
    rs0 += __shfl_xor_sync(0xffffffffu, rs0, 1);
    rs0 += __shfl_xor_sync(0xffffffffu, rs0, 2);
    rs1 += __shfl_xor_sync(0xffffffffu, rs1, 1);
    rs1 += __shfl_xor_sync(0xffffffffu, rs1, 2);
    if ((lane & 3) == 0) {
        sinv[w * 16 + (lane >> 2)]     = 1.0f / rs0;
        sinv[w * 16 + 8 + (lane >> 2)] = 1.0f / rs1;
    }
    __syncthreads();
    const float inv0 = sinv[w * 16 + (lane >> 2)];
    const float inv1 = sinv[w * 16 + 8 + (lane >> 2)];

    // ================== PASS B: 3-term QK + register-direct PV (dbl-buffered) ==================
    float oacc[8][4];
    #pragma unroll
    for (int d = 0; d < 8; ++d)
        #pragma unroll
        for (int e = 0; e < 4; ++e) oacc[d][e] = 0.f;

    const int r0g = q0 + w * 16 + (lane >> 2);
    float* pa_row0 = p_attn + ((size_t)bh * S + r0g) * S;
    float* pa_row1 = p_attn + ((size_t)bh * S + r0g + 8) * S;

    // tile loader: K hi/lo (16KB) + V hi/lo (16KB) into buf
    auto loadB = [&](int t, int buf) {
        const int t0 = t * NK;
        const uint32_t kb = sb + OFF_K + buf * 16384;
        const uint32_t vb = sb + OFF_V + buf * 16384;
        #pragma unroll
        for (int hilo = 0; hilo < 2; ++hilo) {
            const __nv_bfloat16* ksrc = hilo ? g_Klo : g_Khi;
            const __nv_bfloat16* vsrc = hilo ? g_VTlo : g_VThi;
            #pragma unroll
            for (int i = 0; i < 2; ++i) {
                int fi = tid + i * THREADS;
                int row = fi >> 3, c8 = fi & 7;
                uint32_t soff = swz((uint32_t)(row * 128 + c8 * 16));
                CP16(kb + hilo * 8192 + soff,
                     ksrc + ((size_t)bh * S + t0 + row) * Dh + c8 * 8);
                CP16(vb + hilo * 8192 + soff,
                     vsrc + ((size_t)bh * Dh + row) * S + t0 + c8 * 8);
            }
        }
    };

    loadB(0, 0); CP_COMMIT();
    for (int t = 0; t < NT; ++t) {
        const int t0 = t * NK;
        if (t + 1 < NT) { loadB(t + 1, (t + 1) & 1); CP_COMMIT(); CP_WAIT1(); }
        else            { CP_WAIT0(); }
        __syncthreads();
        const uint32_t kb = sb + OFF_K + (t & 1) * 16384;
        const uint32_t vb = sb + OFF_V + (t & 1) * 16384;

        float c[8][4];
        #pragma unroll
        for (int nb = 0; nb < 8; ++nb)
            #pragma unroll
            for (int e = 0; e < 4; ++e) c[nb][e] = 0.f;
        #pragma unroll
        for (int nb2 = 0; nb2 < 4; ++nb2) {
            uint32_t rowb = nb2 * 16 + (lane & 15);
            #pragma unroll
            for (int ks = 0; ks < 4; ++ks) {
                uint32_t ah2 = kb + swz(rowb * 128 + ks * 32 + ((lane >> 4) & 1) * 16);
                uint32_t kh[4], kl[4];
                LDSM4(kh, ah2);
                LDSM4(kl, ah2 + 8192);
                mma_bf16(c[nb2 * 2],     qa[0][ks], kh[0], kh[2]);
                mma_bf16(c[nb2 * 2],     qa[0][ks], kl[0], kl[2]);
                mma_bf16(c[nb2 * 2],     qa[1][ks], kh[0], kh[2]);
                mma_bf16(c[nb2 * 2 + 1], qa[0][ks], kh[1], kh[3]);
                mma_bf16(c[nb2 * 2 + 1], qa[0][ks], kl[1], kl[3]);
                mma_bf16(c[nb2 * 2 + 1], qa[1][ks], kh[1], kh[3]);
            }
        }
        // epilogue: p = mask*exp*inv -> p_attn + register A-fragments
        uint32_t ah[4][4], al[4][4];
        #pragma unroll
        for (int nb = 0; nb < 8; ++nb) {
            int cb = nb * 8 + 2 * (lane & 3);
            int col = t0 + cb;
            float m0 = msf[col], m1 = msf[col + 1];
            float p00 = m0 * __expf(c[nb][0]) * inv0;
            float p01 = m1 * __expf(c[nb][1]) * inv0;
            float p10 = m0 * __expf(c[nb][2]) * inv1;
            float p11 = m1 * __expf(c[nb][3]) * inv1;
            *reinterpret_cast<float2*>(pa_row0 + col) = make_float2(p00, p01);
            *reinterpret_cast<float2*>(pa_row1 + col) = make_float2(p10, p11);
            int ks16 = nb >> 1, h8 = (nb & 1) * 2;
            pack_hilo(p00, p01, ah[ks16][h8 + 0], al[ks16][h8 + 0]);
            pack_hilo(p10, p11, ah[ks16][h8 + 1], al[ks16][h8 + 1]);
        }
        // PV over the 64 keys of this tile
        #pragma unroll
        for (int ks16 = 0; ks16 < 4; ++ks16) {
            uint32_t kcb = ks16 * 32 + ((lane >> 4) & 1) * 16;
            #pragma unroll
            for (int db2 = 0; db2 < 4; ++db2) {
                uint32_t vaddr = vb + swz((uint32_t)((db2 * 16 + (lane & 15)) * 128) + kcb);
                uint32_t vh[4], vl[4];
                LDSM4(vh, vaddr);
                LDSM4(vl, vaddr + 8192);
                mma_bf16(oacc[db2 * 2],     ah[ks16], vh[0], vh[2]);
                mma_bf16(oacc[db2 * 2],     ah[ks16], vl[0], vl[2]);
                mma_bf16(oacc[db2 * 2],     al[ks16], vh[0], vh[2]);
                mma_bf16(oacc[db2 * 2 + 1], ah[ks16], vh[1], vh[3]);
                mma_bf16(oacc[db2 * 2 + 1], ah[ks16], vl[1], vl[3]);
                mma_bf16(oacc[db2 * 2 + 1], al[ks16], vh[1], vh[3]);
            }
        }
        __syncthreads();
    }

    // ---- out store ----
    #pragma unroll
    for (int db = 0; db < 8; ++db) {
        int col = db * 8 + 2 * (lane & 3);
        *reinterpret_cast<float2*>(out + ((size_t)bh * S + r0g) * Dh + col) =
            make_float2(oacc[db][0], oacc[db][1]);
        *reinterpret_cast<float2*>(out + ((size_t)bh * S + r0g + 8) * Dh + col) =
            make_float2(oacc[db][2], oacc[db][3]);
    }
}

extern "C" void kernel_launch(void* const* d_in, const int* in_sizes, int n_in,
                              void* d_out, int out_size) {
    const float* q = (const float*)d_in[0];
    const float* k = (const float*)d_in[1];
    const float* v = (const float*)d_in[2];
    const int* mask = (const int*)d_in[3];

    float* out = (float*)d_out;
    float* p_attn = out + (size_t)Bn * Hn * S * Dh;

    conv_qk<<<NELEM / 4 / THREADS, THREADS>>>(q, k);
    conv_vt<<<dim3(S / 32, Dh / 32, BH), dim3(32, 8)>>>(v);

    cudaFuncSetAttribute(attn_main, cudaFuncAttributeMaxDynamicSharedMemorySize, SMEM_BYTES);
    attn_main<<<dim3(S / MQ, BH), THREADS, SMEM_BYTES>>>(mask, out, p_attn);
}

// round 7
// speedup vs baseline: 3.8166x; 1.0960x over previous
#include <cuda_runtime.h>
#include <cuda_bf16.h>
#include <cstdint>

namespace {
constexpr int Bn = 4, Hn = 16, S = 2048, Dh = 64;
constexpr int BH = Bn * Hn;
constexpr int MQ = 128;
constexpr int NKA = 128;          // pass A keys per tile
constexpr int NTA = S / NKA;      // 16
constexpr int NK = 64;            // pass B keys per tile
constexpr int NT = S / NK;        // 32
constexpr int THREADS = 256;
constexpr int NELEM = BH * S * Dh;
constexpr float LOG2E = 1.4426950408889634f;

constexpr int OFF_K   = 0;              // pass B: [2 buf][hi/lo 8KB each] ; pass A: [2 buf][16KB hi]
constexpr int OFF_V   = 32768;          // pass B: [2 buf][hi/lo 8KB each]
constexpr int OFF_MS  = 65536;          // 2048 f32
constexpr int OFF_INV = 73728;          // 128 f32
constexpr unsigned SMEM_BYTES = OFF_INV + 512;   // 74,240 B -> 2 CTAs/SM
}

__device__ __nv_bfloat16 g_Qhi[NELEM], g_Qlo[NELEM];
__device__ __nv_bfloat16 g_Khi[NELEM], g_Klo[NELEM];
__device__ __nv_bfloat16 g_VThi[NELEM], g_VTlo[NELEM];   // [bh][d][s]

__device__ __forceinline__ uint32_t s2u(const void* p) {
    uint32_t a;
    asm("{ .reg .u64 t; cvta.to.shared.u64 t, %1; cvt.u32.u64 %0, t; }" : "=r"(a) : "l"(p));
    return a;
}
__device__ __forceinline__ uint32_t swz(uint32_t o) { return o ^ ((o >> 3) & 0x70); }

#define LDSM4(r, a) \
    asm volatile("ldmatrix.sync.aligned.m8n8.x4.shared.b16 {%0,%1,%2,%3},[%4];" \
                 : "=r"((r)[0]), "=r"((r)[1]), "=r"((r)[2]), "=r"((r)[3]) : "r"(a))
#define CP16(dst, src) \
    asm volatile("cp.async.ca.shared.global [%0], [%1], 16;" :: "r"(dst), "l"(src))
#define CP_COMMIT() asm volatile("cp.async.commit_group;" ::: "memory")
#define CP_WAIT0()  asm volatile("cp.async.wait_group 0;" ::: "memory")
#define CP_WAIT1()  asm volatile("cp.async.wait_group 1;" ::: "memory")

__device__ __forceinline__ void mma_bf16(float c[4], const uint32_t a[4],
                                         uint32_t b0, uint32_t b1) {
    asm volatile(
        "mma.sync.aligned.m16n8k16.row.col.f32.bf16.bf16.f32 "
        "{%0,%1,%2,%3},{%4,%5,%6,%7},{%8,%9},{%0,%1,%2,%3};"
        : "+f"(c[0]), "+f"(c[1]), "+f"(c[2]), "+f"(c[3])
        : "r"(a[0]), "r"(a[1]), "r"(a[2]), "r"(a[3]), "r"(b0), "r"(b1));
}

__device__ __forceinline__ float ex2f(float x) {
    float r;
    asm("ex2.approx.ftz.f32 %0, %1;" : "=f"(r) : "f"(x));
    return r;
}

// integer-trick bf16 hi/lo split of a pair; hi via round-half-up (residual near-exact)
__device__ __forceinline__ void pack2(float x, float y, uint32_t& hi, uint32_t& lo) {
    uint32_t rx = __float_as_uint(x) + 0x8000u;
    uint32_t ry = __float_as_uint(y) + 0x8000u;
    hi = __byte_perm(rx, ry, 0x7632);
    float hx = __uint_as_float(rx & 0xFFFF0000u);
    float hy = __uint_as_float(ry & 0xFFFF0000u);
    asm("cvt.rn.bf16x2.f32 %0, %1, %2;" : "=r"(lo) : "f"(y - hy), "f"(x - hx));
}

__device__ __forceinline__ void fsplit(float x, __nv_bfloat16& h, __nv_bfloat16& l) {
    h = __float2bfloat16_rn(x);
    l = __float2bfloat16_rn(x - __bfloat162float(h));
}
__device__ __forceinline__ uint32_t pack_hi(float x, float y) {
    __nv_bfloat162 t;
    t.x = __float2bfloat16_rn(x);
    t.y = __float2bfloat16_rn(y);
    return *reinterpret_cast<uint32_t*>(&t);
}
__device__ __forceinline__ uint32_t pack_lo(float x, float y) {
    __nv_bfloat162 t;
    t.x = __float2bfloat16_rn(x - __bfloat162float(__float2bfloat16_rn(x)));
    t.y = __float2bfloat16_rn(y - __bfloat162float(__float2bfloat16_rn(y)));
    return *reinterpret_cast<uint32_t*>(&t);
}

// ---------------- pre-kernels ----------------
__global__ void conv_qk(const float* __restrict__ q, const float* __restrict__ k) {
    size_t i4 = (size_t)blockIdx.x * blockDim.x + threadIdx.x;
    size_t e = i4 * 4;
    float4 qv = *reinterpret_cast<const float4*>(q + e);
    float4 kv = *reinterpret_cast<const float4*>(k + e);
    qv.x *= 0.125f; qv.y *= 0.125f; qv.z *= 0.125f; qv.w *= 0.125f;
    uint2 w;
    w.x = pack_hi(qv.x, qv.y); w.y = pack_hi(qv.z, qv.w);
    *reinterpret_cast<uint2*>(g_Qhi + e) = w;
    w.x = pack_lo(qv.x, qv.y); w.y = pack_lo(qv.z, qv.w);
    *reinterpret_cast<uint2*>(g_Qlo + e) = w;
    w.x = pack_hi(kv.x, kv.y); w.y = pack_hi(kv.z, kv.w);
    *reinterpret_cast<uint2*>(g_Khi + e) = w;
    w.x = pack_lo(kv.x, kv.y); w.y = pack_lo(kv.z, kv.w);
    *reinterpret_cast<uint2*>(g_Klo + e) = w;
}

__global__ void conv_vt(const float* __restrict__ v) {
    __shared__ float t[32][33];
    const int bh = blockIdx.z, s0 = blockIdx.x * 32, d0 = blockIdx.y * 32;
    const int tx = threadIdx.x, ty = threadIdx.y;   // (32, 8)
    #pragma unroll
    for (int j = 0; j < 4; ++j)
        t[ty + 8 * j][tx] = v[((size_t)bh * S + s0 + ty + 8 * j) * Dh + d0 + tx];
    __syncthreads();
    #pragma unroll
    for (int j = 0; j < 4; ++j) {
        float x = t[tx][ty + 8 * j];
        __nv_bfloat16 h, l;
        fsplit(x, h, l);
        size_t o = ((size_t)bh * Dh + d0 + ty + 8 * j) * S + s0 + tx;
        g_VThi[o] = h; g_VTlo[o] = l;
    }
}

// ---------------- main kernel ----------------
__global__ __launch_bounds__(THREADS, 2)
void attn_main(const int* __restrict__ mask, float* __restrict__ out,
               float* __restrict__ p_attn)
{
    extern __shared__ char sm[];
    const uint32_t sb = s2u(sm);
    const int tid = threadIdx.x;
    const int w = tid >> 5, lane = tid & 31;
    const int qt = blockIdx.x, bh = blockIdx.y;
    const int b = bh >> 4;
    const int q0 = qt * MQ;
    float* msf  = reinterpret_cast<float*>(sm + OFF_MS);
    float* sinv = reinterpret_cast<float*>(sm + OFF_INV);

    // ---- prologue: Q (hi/lo) into [0,32KB) + mask ----
    #pragma unroll
    for (int buf = 0; buf < 2; ++buf) {
        const __nv_bfloat16* src = buf ? g_Qlo : g_Qhi;
        #pragma unroll
        for (int i = 0; i < 4; ++i) {
            int fi = tid + i * THREADS;
            int row = fi >> 3, c8 = fi & 7;
            CP16(sb + buf * 16384 + swz((uint32_t)(row * 128 + c8 * 16)),
                 src + ((size_t)bh * S + q0 + row) * Dh + c8 * 8);
        }
    }
    for (int i = tid; i < S; i += THREADS)
        msf[i] = (mask[b * S + i] != 0) ? 1.0f : 0.0f;
    CP_COMMIT(); CP_WAIT0();
    __syncthreads();

    // ---- Q fragments (persistent registers) ----
    uint32_t qa[2][4][4];
    #pragma unroll
    for (int buf = 0; buf < 2; ++buf)
        #pragma unroll
        for (int ks = 0; ks < 4; ++ks) {
            uint32_t a = sb + buf * 16384 +
                swz((uint32_t)((w * 16 + (lane & 15)) * 128 + ks * 32 +
                               ((lane >> 4) & 1) * 16));
            LDSM4(qa[buf][ks], a);
        }
    __syncthreads();   // Q smem free for reuse

    // ================== PASS A: rowsums (1-term, hi only, 128-key tiles) ==================
    float rs0 = 0.f, rs1 = 0.f;
    {
        #pragma unroll
        for (int i = 0; i < 4; ++i) {   // preload tile 0 (16KB)
            int fi = tid + i * THREADS;
            int row = fi >> 3, c8 = fi & 7;
            CP16(sb + OFF_K + swz((uint32_t)(row * 128 + c8 * 16)),
                 g_Khi + ((size_t)bh * S + row) * Dh + c8 * 8);
        }
        CP_COMMIT();
        for (int t = 0; t < NTA; ++t) {
            const int t0 = t * NKA;
            if (t + 1 < NTA) {
                const uint32_t dstb = sb + OFF_K + ((t + 1) & 1) * 16384;
                #pragma unroll
                for (int i = 0; i < 4; ++i) {
                    int fi = tid + i * THREADS;
                    int row = fi >> 3, c8 = fi & 7;
                    CP16(dstb + swz((uint32_t)(row * 128 + c8 * 16)),
                         g_Khi + ((size_t)bh * S + t0 + NKA + row) * Dh + c8 * 8);
                }
                CP_COMMIT(); CP_WAIT1();
            } else {
                CP_WAIT0();
            }
            __syncthreads();
            const uint32_t kbase = sb + OFF_K + (t & 1) * 16384;
            #pragma unroll
            for (int g = 0; g < 8; ++g) {          // 16-key chunks: QK then exp (interleavable)
                float c0[4] = {0.f, 0.f, 0.f, 0.f};
                float c1[4] = {0.f, 0.f, 0.f, 0.f};
                uint32_t rowb = g * 16 + (lane & 15);
                #pragma unroll
                for (int ks = 0; ks < 4; ++ks) {
                    uint32_t kh[4];
                    LDSM4(kh, kbase + swz(rowb * 128 + ks * 32 + ((lane >> 4) & 1) * 16));
                    mma_bf16(c0, qa[0][ks], kh[0], kh[2]);
                    mma_bf16(c1, qa[0][ks], kh[1], kh[3]);
                }
                int colA = t0 + g * 16 + 2 * (lane & 3);
                float2 mA = *reinterpret_cast<const float2*>(msf + colA);
                float2 mB = *reinterpret_cast<const float2*>(msf + colA + 8);
                rs0 += mA.x * ex2f(c0[0] * LOG2E) + mA.y * ex2f(c0[1] * LOG2E);
                rs1 += mA.x * ex2f(c0[2] * LOG2E) + mA.y * ex2f(c0[3] * LOG2E);
                rs0 += mB.x * ex2f(c1[0] * LOG2E) + mB.y * ex2f(c1[1] * LOG2E);
                rs1 += mB.x * ex2f(c1[2] * LOG2E) + mB.y * ex2f(c1[3] * LOG2E);
            }
            __syncthreads();
        }
    }
    rs0 += __shfl_xor_sync(0xffffffffu, rs0, 1);
    rs0 += __shfl_xor_sync(0xffffffffu, rs0, 2);
    rs1 += __shfl_xor_sync(0xffffffffu, rs1, 1);
    rs1 += __shfl_xor_sync(0xffffffffu, rs1, 2);
    if ((lane & 3) == 0) {
        sinv[w * 16 + (lane >> 2)]     = rs0;
        sinv[w * 16 + 8 + (lane >> 2)] = rs1;
    }
    __syncthreads();
    const float linv0 = -__log2f(sinv[w * 16 + (lane >> 2)]);
    const float linv1 = -__log2f(sinv[w * 16 + 8 + (lane >> 2)]);

    // ================== PASS B: fused QK→epilogue→PV 16-key chunks ==================
    float oacc[8][4];
    #pragma unroll
    for (int d = 0; d < 8; ++d)
        #pragma unroll
        for (int e = 0; e < 4; ++e) oacc[d][e] = 0.f;

    const int r0g = q0 + w * 16 + (lane >> 2);
    float* pa_row0 = p_attn + ((size_t)bh * S + r0g) * S;
    float* pa_row1 = p_attn + ((size_t)bh * S + r0g + 8) * S;

    auto loadB = [&](int t, int buf) {
        const int t0 = t * NK;
        const uint32_t kbuf = sb + OFF_K + buf * 16384;
        const uint32_t vbuf = sb + OFF_V + buf * 16384;
        #pragma unroll
        for (int hilo = 0; hilo < 2; ++hilo) {
            const __nv_bfloat16* ksrc = hilo ? g_Klo : g_Khi;
            const __nv_bfloat16* vsrc = hilo ? g_VTlo : g_VThi;
            #pragma unroll
            for (int i = 0; i < 2; ++i) {
                int fi = tid + i * THREADS;
                int row = fi >> 3, c8 = fi & 7;
                uint32_t soff = swz((uint32_t)(row * 128 + c8 * 16));
                CP16(kbuf + hilo * 8192 + soff,
                     ksrc + ((size_t)bh * S + t0 + row) * Dh + c8 * 8);
                CP16(vbuf + hilo * 8192 + soff,
                     vsrc + ((size_t)bh * Dh + row) * S + t0 + c8 * 8);
            }
        }
    };

    loadB(0, 0); CP_COMMIT();
    for (int t = 0; t < NT; ++t) {
        const int t0 = t * NK;
        if (t + 1 < NT) { loadB(t + 1, (t + 1) & 1); CP_COMMIT(); CP_WAIT1(); }
        else            { CP_WAIT0(); }
        __syncthreads();
        const uint32_t kb = sb + OFF_K + (t & 1) * 16384;
        const uint32_t vb = sb + OFF_V + (t & 1) * 16384;

        #pragma unroll
        for (int g = 0; g < 4; ++g) {
            // --- QK for this 16-key chunk (3-term) ---
            float c0[4] = {0.f, 0.f, 0.f, 0.f};
            float c1[4] = {0.f, 0.f, 0.f, 0.f};
            uint32_t rowb = g * 16 + (lane & 15);
            #pragma unroll
            for (int ks = 0; ks < 4; ++ks) {
                uint32_t ah2 = kb + swz(rowb * 128 + ks * 32 + ((lane >> 4) & 1) * 16);
                uint32_t kh[4], kl[4];
                LDSM4(kh, ah2);
                LDSM4(kl, ah2 + 8192);
                mma_bf16(c0, qa[0][ks], kh[0], kh[2]);
                mma_bf16(c0, qa[0][ks], kl[0], kl[2]);
                mma_bf16(c0, qa[1][ks], kh[0], kh[2]);
                mma_bf16(c1, qa[0][ks], kh[1], kh[3]);
                mma_bf16(c1, qa[0][ks], kl[1], kl[3]);
                mma_bf16(c1, qa[1][ks], kh[1], kh[3]);
            }
            // --- epilogue: p = m * 2^(s*log2e + linv) ; store + pack ---
            int colA = t0 + g * 16 + 2 * (lane & 3);
            float2 mA = *reinterpret_cast<const float2*>(msf + colA);
            float2 mB = *reinterpret_cast<const float2*>(msf + colA + 8);
            float p00 = mA.x * ex2f(fmaf(c0[0], LOG2E, linv0));
            float p01 = mA.y * ex2f(fmaf(c0[1], LOG2E, linv0));
            float p10 = mA.x * ex2f(fmaf(c0[2], LOG2E, linv1));
            float p11 = mA.y * ex2f(fmaf(c0[3], LOG2E, linv1));
            float q00 = mB.x * ex2f(fmaf(c1[0], LOG2E, linv0));
            float q01 = mB.y * ex2f(fmaf(c1[1], LOG2E, linv0));
            float q10 = mB.x * ex2f(fmaf(c1[2], LOG2E, linv1));
            float q11 = mB.y * ex2f(fmaf(c1[3], LOG2E, linv1));
            *reinterpret_cast<float2*>(pa_row0 + colA)     = make_float2(p00, p01);
            *reinterpret_cast<float2*>(pa_row0 + colA + 8) = make_float2(q00, q01);
            *reinterpret_cast<float2*>(pa_row1 + colA)     = make_float2(p10, p11);
            *reinterpret_cast<float2*>(pa_row1 + colA + 8) = make_float2(q10, q11);
            uint32_t ah[4], al[4];
            pack2(p00, p01, ah[0], al[0]);
            pack2(p10, p11, ah[1], al[1]);
            pack2(q00, q01, ah[2], al[2]);
            pack2(q10, q11, ah[3], al[3]);
            // --- PV for this chunk ---
            uint32_t kcb = g * 32 + ((lane >> 4) & 1) * 16;
            #pragma unroll
            for (int db2 = 0; db2 < 4; ++db2) {
                uint32_t vaddr = vb + swz((uint32_t)((db2 * 16 + (lane & 15)) * 128) + kcb);
                uint32_t vh[4], vl[4];
                LDSM4(vh, vaddr);
                LDSM4(vl, vaddr + 8192);
                mma_bf16(oacc[db2 * 2],     ah, vh[0], vh[2]);
                mma_bf16(oacc[db2 * 2],     ah, vl[0], vl[2]);
                mma_bf16(oacc[db2 * 2],     al, vh[0], vh[2]);
                mma_bf16(oacc[db2 * 2 + 1], ah, vh[1], vh[3]);
                mma_bf16(oacc[db2 * 2 + 1], ah, vl[1], vl[3]);
                mma_bf16(oacc[db2 * 2 + 1], al, vh[1], vh[3]);
            }
        }
        __syncthreads();
    }

    // ---- out store ----
    #pragma unroll
    for (int db = 0; db < 8; ++db) {
        int col = db * 8 + 2 * (lane & 3);
        *reinterpret_cast<float2*>(out + ((size_t)bh * S + r0g) * Dh + col) =
            make_float2(oacc[db][0], oacc[db][1]);
        *reinterpret_cast<float2*>(out + ((size_t)bh * S + r0g + 8) * Dh + col) =
            make_float2(oacc[db][2], oacc[db][3]);
    }
}

extern "C" void kernel_launch(void* const* d_in, const int* in_sizes, int n_in,
                              void* d_out, int out_size) {
    const float* q = (const float*)d_in[0];
    const float* k = (const float*)d_in[1];
    const float* v = (const float*)d_in[2];
    const int* mask = (const int*)d_in[3];

    float* out = (float*)d_out;
    float* p_attn = out + (size_t)Bn * Hn * S * Dh;

    conv_qk<<<NELEM / 4 / THREADS, THREADS>>>(q, k);
    conv_vt<<<dim3(S / 32, Dh / 32, BH), dim3(32, 8)>>>(v);

    cudaFuncSetAttribute(attn_main, cudaFuncAttributeMaxDynamicSharedMemorySize, SMEM_BYTES);
    attn_main<<<dim3(S / MQ, BH), THREADS, SMEM_BYTES>>>(mask, out, p_attn);
}

// round 9
// speedup vs baseline: 3.8668x; 1.0132x over previous
#include <cuda_runtime.h>
#include <cuda_bf16.h>
#include <cstdint>

namespace {
constexpr int Bn = 4, Hn = 16, S = 2048, Dh = 64;
constexpr int BH = Bn * Hn;
constexpr int MQ = 128;
constexpr int NKA = 128;          // pass A keys per tile
constexpr int NTA = S / NKA;      // 16
constexpr int NK = 64;            // pass B keys per tile
constexpr int NT = S / NK;        // 32
constexpr int THREADS = 256;
constexpr int NELEM = BH * S * Dh;
constexpr float LOG2E = 1.4426950408889634f;
constexpr int NUNITS = BH * (S / MQ);   // 1024 units per pass
constexpr int GRID = 296;               // 2 CTAs/SM x 148 SMs (persistent)

constexpr int OFF_K   = 0;              // [2 buf][16KB]
constexpr int OFF_V   = 32768;          // [2 buf][16KB]
constexpr int OFF_MS  = 65536;          // 2048 f32
constexpr unsigned SMEM_BYTES = OFF_MS + S * 4;   // 73,728 B -> 2 CTAs/SM
}

__device__ __nv_bfloat16 g_Qhi[NELEM], g_Qlo[NELEM];
__device__ __nv_bfloat16 g_Khi[NELEM], g_Klo[NELEM];
__device__ __nv_bfloat16 g_VThi[NELEM], g_VTlo[NELEM];   // [bh][d][s]

__device__ unsigned g_ctr;
__device__ unsigned g_flag[NUNITS];
__device__ float    g_linv[NUNITS][MQ];

__device__ __forceinline__ uint32_t s2u(const void* p) {
    uint32_t a;
    asm("{ .reg .u64 t; cvta.to.shared.u64 t, %1; cvt.u32.u64 %0, t; }" : "=r"(a) : "l"(p));
    return a;
}
__device__ __forceinline__ uint32_t swz(uint32_t o) { return o ^ ((o >> 3) & 0x70); }

#define LDSM4(r, a) \
    asm volatile("ldmatrix.sync.aligned.m8n8.x4.shared.b16 {%0,%1,%2,%3},[%4];" \
                 : "=r"((r)[0]), "=r"((r)[1]), "=r"((r)[2]), "=r"((r)[3]) : "r"(a))
#define CP16(dst, src) \
    asm volatile("cp.async.ca.shared.global [%0], [%1], 16;" :: "r"(dst), "l"(src))
#define CP_COMMIT() asm volatile("cp.async.commit_group;" ::: "memory")
#define CP_WAIT0()  asm volatile("cp.async.wait_group 0;" ::: "memory")
#define CP_WAIT1()  asm volatile("cp.async.wait_group 1;" ::: "memory")

__device__ __forceinline__ void mma_bf16(float c[4], const uint32_t a[4],
                                         uint32_t b0, uint32_t b1) {
    asm volatile(
        "mma.sync.aligned.m16n8k16.row.col.f32.bf16.bf16.f32 "
        "{%0,%1,%2,%3},{%4,%5,%6,%7},{%8,%9},{%0,%1,%2,%3};"
        : "+f"(c[0]), "+f"(c[1]), "+f"(c[2]), "+f"(c[3])
        : "r"(a[0]), "r"(a[1]), "r"(a[2]), "r"(a[3]), "r"(b0), "r"(b1));
}

__device__ __forceinline__ float ex2f(float x) {
    float r;
    asm("ex2.approx.ftz.f32 %0, %1;" : "=f"(r) : "f"(x));
    return r;
}

// integer-trick bf16 hi/lo split of a pair; hi via round-half-up (residual near-exact)
__device__ __forceinline__ void pack2(float x, float y, uint32_t& hi, uint32_t& lo) {
    uint32_t rx = __float_as_uint(x) + 0x8000u;
    uint32_t ry = __float_as_uint(y) + 0x8000u;
    hi = __byte_perm(rx, ry, 0x7632);
    float hx = __uint_as_float(rx & 0xFFFF0000u);
    float hy = __uint_as_float(ry & 0xFFFF0000u);
    asm("cvt.rn.bf16x2.f32 %0, %1, %2;" : "=r"(lo) : "f"(y - hy), "f"(x - hx));
}

__device__ __forceinline__ void fsplit(float x, __nv_bfloat16& h, __nv_bfloat16& l) {
    h = __float2bfloat16_rn(x);
    l = __float2bfloat16_rn(x - __bfloat162float(h));
}
__device__ __forceinline__ uint32_t pack_hi(float x, float y) {
    __nv_bfloat162 t;
    t.x = __float2bfloat16_rn(x);
    t.y = __float2bfloat16_rn(y);
    return *reinterpret_cast<uint32_t*>(&t);
}
__device__ __forceinline__ uint32_t pack_lo(float x, float y) {
    __nv_bfloat162 t;
    t.x = __float2bfloat16_rn(x - __bfloat162float(__float2bfloat16_rn(x)));
    t.y = __float2bfloat16_rn(y - __bfloat162float(__float2bfloat16_rn(y)));
    return *reinterpret_cast<uint32_t*>(&t);
}

// ---------------- pre-kernels ----------------
__global__ void conv_qk(const float* __restrict__ q, const float* __restrict__ k) {
    // per-launch reset of the persistent-queue state (runs before attn_persist)
    if (blockIdx.x == 0) {
        if (threadIdx.x == 0) g_ctr = 0u;
        for (int i = threadIdx.x; i < NUNITS; i += blockDim.x) g_flag[i] = 0u;
    }
    size_t i4 = (size_t)blockIdx.x * blockDim.x + threadIdx.x;
    size_t e = i4 * 4;
    float4 qv = *reinterpret_cast<const float4*>(q + e);
    float4 kv = *reinterpret_cast<const float4*>(k + e);
    qv.x *= 0.125f; qv.y *= 0.125f; qv.z *= 0.125f; qv.w *= 0.125f;
    uint2 w;
    w.x = pack_hi(qv.x, qv.y); w.y = pack_hi(qv.z, qv.w);
    *reinterpret_cast<uint2*>(g_Qhi + e) = w;
    w.x = pack_lo(qv.x, qv.y); w.y = pack_lo(qv.z, qv.w);
    *reinterpret_cast<uint2*>(g_Qlo + e) = w;
    w.x = pack_hi(kv.x, kv.y); w.y = pack_hi(kv.z, kv.w);
    *reinterpret_cast<uint2*>(g_Khi + e) = w;
    w.x = pack_lo(kv.x, kv.y); w.y = pack_lo(kv.z, kv.w);
    *reinterpret_cast<uint2*>(g_Klo + e) = w;
}

__global__ void conv_vt(const float* __restrict__ v) {
    __shared__ float t[32][33];
    const int bh = blockIdx.z, s0 = blockIdx.x * 32, d0 = blockIdx.y * 32;
    const int tx = threadIdx.x, ty = threadIdx.y;   // (32, 8)
    #pragma unroll
    for (int j = 0; j < 4; ++j)
        t[ty + 8 * j][tx] = v[((size_t)bh * S + s0 + ty + 8 * j) * Dh + d0 + tx];
    __syncthreads();
    #pragma unroll
    for (int j = 0; j < 4; ++j) {
        float x = t[tx][ty + 8 * j];
        __nv_bfloat16 h, l;
        fsplit(x, h, l);
        size_t o = ((size_t)bh * Dh + d0 + ty + 8 * j) * S + s0 + tx;
        g_VThi[o] = h; g_VTlo[o] = l;
    }
}

// ---------------- persistent main kernel ----------------
__global__ __launch_bounds__(THREADS, 2)
void attn_persist(const int* __restrict__ mask, float* __restrict__ out,
                  float* __restrict__ p_attn)
{
    extern __shared__ char sm[];
    __shared__ unsigned s_uid;
    const uint32_t sb = s2u(sm);
    const int tid = threadIdx.x;
    const int w = tid >> 5, lane = tid & 31;
    float* msf = reinterpret_cast<float*>(sm + OFF_MS);

    for (;;) {
        __syncthreads();   // previous unit fully done with smem + s_uid
        if (tid == 0) s_uid = atomicAdd(&g_ctr, 1u);
        __syncthreads();
        const unsigned uid = s_uid;
        if (uid >= 2u * NUNITS) break;
        const bool isA = uid < (unsigned)NUNITS;
        const int u  = isA ? (int)uid : (int)(uid - NUNITS);
        const int qt = u & 15, bh = u >> 4;
        const int b  = bh >> 4;
        const int q0 = qt * MQ;

        // mask row for this batch
        for (int i = tid; i < S; i += THREADS)
            msf[i] = (mask[b * S + i] != 0) ? 1.0f : 0.0f;

        if (isA) {
            // ======== PASS A UNIT: rowsums (1-term, K-hi only) ========
            #pragma unroll
            for (int i = 0; i < 4; ++i) {   // stage Q-hi
                int fi = tid + i * THREADS;
                int row = fi >> 3, c8 = fi & 7;
                CP16(sb + OFF_K + swz((uint32_t)(row * 128 + c8 * 16)),
                     g_Qhi + ((size_t)bh * S + q0 + row) * Dh + c8 * 8);
            }
            CP_COMMIT(); CP_WAIT0(); __syncthreads();
            uint32_t qa0[4][4];
            #pragma unroll
            for (int ks = 0; ks < 4; ++ks) {
                uint32_t a = sb + OFF_K +
                    swz((uint32_t)((w * 16 + (lane & 15)) * 128 + ks * 32 +
                                   ((lane >> 4) & 1) * 16));
                LDSM4(qa0[ks], a);
            }
            __syncthreads();

            float rs0 = 0.f, rs1 = 0.f;
            #pragma unroll
            for (int i = 0; i < 4; ++i) {   // preload tile 0
                int fi = tid + i * THREADS;
                int row = fi >> 3, c8 = fi & 7;
                CP16(sb + OFF_K + swz((uint32_t)(row * 128 + c8 * 16)),
                     g_Khi + ((size_t)bh * S + row) * Dh + c8 * 8);
            }
            CP_COMMIT();
            for (int t = 0; t < NTA; ++t) {
                const int t0 = t * NKA;
                if (t + 1 < NTA) {
                    const uint32_t dstb = sb + OFF_K + ((t + 1) & 1) * 16384;
                    #pragma unroll
                    for (int i = 0; i < 4; ++i) {
                        int fi = tid + i * THREADS;
                        int row = fi >> 3, c8 = fi & 7;
                        CP16(dstb + swz((uint32_t)(row * 128 + c8 * 16)),
                             g_Khi + ((size_t)bh * S + t0 + NKA + row) * Dh + c8 * 8);
                    }
                    CP_COMMIT(); CP_WAIT1();
                } else {
                    CP_WAIT0();
                }
                __syncthreads();
                const uint32_t kbase = sb + OFF_K + (t & 1) * 16384;
                #pragma unroll
                for (int g = 0; g < 8; ++g) {
                    float c0[4] = {0.f, 0.f, 0.f, 0.f};
                    float c1[4] = {0.f, 0.f, 0.f, 0.f};
                    uint32_t rowb = g * 16 + (lane & 15);
                    #pragma unroll
                    for (int ks = 0; ks < 4; ++ks) {
                        uint32_t kh[4];
                        LDSM4(kh, kbase + swz(rowb * 128 + ks * 32 + ((lane >> 4) & 1) * 16));
                        mma_bf16(c0, qa0[ks], kh[0], kh[2]);
                        mma_bf16(c1, qa0[ks], kh[1], kh[3]);
                    }
                    int colA = t0 + g * 16 + 2 * (lane & 3);
                    float2 mA = *reinterpret_cast<const float2*>(msf + colA);
                    float2 mB = *reinterpret_cast<const float2*>(msf + colA + 8);
                    rs0 += mA.x * ex2f(c0[0] * LOG2E) + mA.y * ex2f(c0[1] * LOG2E);
                    rs1 += mA.x * ex2f(c0[2] * LOG2E) + mA.y * ex2f(c0[3] * LOG2E);
                    rs0 += mB.x * ex2f(c1[0] * LOG2E) + mB.y * ex2f(c1[1] * LOG2E);
                    rs1 += mB.x * ex2f(c1[2] * LOG2E) + mB.y * ex2f(c1[3] * LOG2E);
                }
                __syncthreads();
            }
            rs0 += __shfl_xor_sync(0xffffffffu, rs0, 1);
            rs0 += __shfl_xor_sync(0xffffffffu, rs0, 2);
            rs1 += __shfl_xor_sync(0xffffffffu, rs1, 1);
            rs1 += __shfl_xor_sync(0xffffffffu, rs1, 2);
            if ((lane & 3) == 0) {
                g_linv[u][w * 16 + (lane >> 2)]     = -__log2f(rs0);
                g_linv[u][w * 16 + 8 + (lane >> 2)] = -__log2f(rs1);
            }
            __syncthreads();
            __threadfence();                       // release: linv visible before flag
            if (tid == 0) atomicExch(&g_flag[u], 1u);
        } else {
            // ======== PASS B UNIT: p_attn + out (3-term QK, fused PV) ========
            #pragma unroll
            for (int buf = 0; buf < 2; ++buf) {    // stage Q hi/lo
                const __nv_bfloat16* src = buf ? g_Qlo : g_Qhi;
                #pragma unroll
                for (int i = 0; i < 4; ++i) {
                    int fi = tid + i * THREADS;
                    int row = fi >> 3, c8 = fi & 7;
                    CP16(sb + OFF_K + buf * 16384 + swz((uint32_t)(row * 128 + c8 * 16)),
                         src + ((size_t)bh * S + q0 + row) * Dh + c8 * 8);
                }
            }
            CP_COMMIT(); CP_WAIT0(); __syncthreads();
            uint32_t qa[2][4][4];
            #pragma unroll
            for (int buf = 0; buf < 2; ++buf)
                #pragma unroll
                for (int ks = 0; ks < 4; ++ks) {
                    uint32_t a = sb + OFF_K + buf * 16384 +
                        swz((uint32_t)((w * 16 + (lane & 15)) * 128 + ks * 32 +
                                       ((lane >> 4) & 1) * 16));
                    LDSM4(qa[buf][ks], a);
                }
            // acquire rowsums from the matching A unit
            if (tid == 0) {
                while (atomicAdd(&g_flag[u], 0u) == 0u) __nanosleep(200);
                __threadfence();
            }
            __syncthreads();
            const float linv0 = __ldcg(&g_linv[u][w * 16 + (lane >> 2)]);
            const float linv1 = __ldcg(&g_linv[u][w * 16 + 8 + (lane >> 2)]);

            float oacc[8][4];
            #pragma unroll
            for (int d = 0; d < 8; ++d)
                #pragma unroll
                for (int e = 0; e < 4; ++e) oacc[d][e] = 0.f;

            const int r0g = q0 + w * 16 + (lane >> 2);
            float* pa_row0 = p_attn + ((size_t)bh * S + r0g) * S;
            float* pa_row1 = p_attn + ((size_t)bh * S + r0g + 8) * S;

            auto loadB = [&](int t, int buf) {
                const int t0 = t * NK;
                const uint32_t kbuf = sb + OFF_K + buf * 16384;
                const uint32_t vbuf = sb + OFF_V + buf * 16384;
                #pragma unroll
                for (int hilo = 0; hilo < 2; ++hilo) {
                    const __nv_bfloat16* ksrc = hilo ? g_Klo : g_Khi;
                    const __nv_bfloat16* vsrc = hilo ? g_VTlo : g_VThi;
                    #pragma unroll
                    for (int i = 0; i < 2; ++i) {
                        int fi = tid + i * THREADS;
                        int row = fi >> 3, c8 = fi & 7;
                        uint32_t soff = swz((uint32_t)(row * 128 + c8 * 16));
                        CP16(kbuf + hilo * 8192 + soff,
                             ksrc + ((size_t)bh * S + t0 + row) * Dh + c8 * 8);
                        CP16(vbuf + hilo * 8192 + soff,
                             vsrc + ((size_t)bh * Dh + row) * S + t0 + c8 * 8);
                    }
                }
            };

            __syncthreads();   // Q staging reads done before K tiles overwrite
            loadB(0, 0); CP_COMMIT();
            for (int t = 0; t < NT; ++t) {
                const int t0 = t * NK;
                if (t + 1 < NT) { loadB(t + 1, (t + 1) & 1); CP_COMMIT(); CP_WAIT1(); }
                else            { CP_WAIT0(); }
                __syncthreads();
                const uint32_t kb = sb + OFF_K + (t & 1) * 16384;
                const uint32_t vb = sb + OFF_V + (t & 1) * 16384;

                #pragma unroll
                for (int g = 0; g < 4; ++g) {
                    float c0[4] = {0.f, 0.f, 0.f, 0.f};
                    float c1[4] = {0.f, 0.f, 0.f, 0.f};
                    uint32_t rowb = g * 16 + (lane & 15);
                    #pragma unroll
                    for (int ks = 0; ks < 4; ++ks) {
                        uint32_t ah2 = kb + swz(rowb * 128 + ks * 32 + ((lane >> 4) & 1) * 16);
                        uint32_t kh[4], kl[4];
                        LDSM4(kh, ah2);
                        LDSM4(kl, ah2 + 8192);
                        mma_bf16(c0, qa[0][ks], kh[0], kh[2]);
                        mma_bf16(c0, qa[0][ks], kl[0], kl[2]);
                        mma_bf16(c0, qa[1][ks], kh[0], kh[2]);
                        mma_bf16(c1, qa[0][ks], kh[1], kh[3]);
                        mma_bf16(c1, qa[0][ks], kl[1], kl[3]);
                        mma_bf16(c1, qa[1][ks], kh[1], kh[3]);
                    }
                    int colA = t0 + g * 16 + 2 * (lane & 3);
                    float2 mA = *reinterpret_cast<const float2*>(msf + colA);
                    float2 mB = *reinterpret_cast<const float2*>(msf + colA + 8);
                    float p00 = mA.x * ex2f(fmaf(c0[0], LOG2E, linv0));
                    float p01 = mA.y * ex2f(fmaf(c0[1], LOG2E, linv0));
                    float p10 = mA.x * ex2f(fmaf(c0[2], LOG2E, linv1));
                    float p11 = mA.y * ex2f(fmaf(c0[3], LOG2E, linv1));
                    float q00 = mB.x * ex2f(fmaf(c1[0], LOG2E, linv0));
                    float q01 = mB.y * ex2f(fmaf(c1[1], LOG2E, linv0));
                    float q10 = mB.x * ex2f(fmaf(c1[2], LOG2E, linv1));
                    float q11 = mB.y * ex2f(fmaf(c1[3], LOG2E, linv1));
                    *reinterpret_cast<float2*>(pa_row0 + colA)     = make_float2(p00, p01);
                    *reinterpret_cast<float2*>(pa_row0 + colA + 8) = make_float2(q00, q01);
                    *reinterpret_cast<float2*>(pa_row1 + colA)     = make_float2(p10, p11);
                    *reinterpret_cast<float2*>(pa_row1 + colA + 8) = make_float2(q10, q11);
                    uint32_t ah[4], al[4];
                    pack2(p00, p01, ah[0], al[0]);
                    pack2(p10, p11, ah[1], al[1]);
                    pack2(q00, q01, ah[2], al[2]);
                    pack2(q10, q11, ah[3], al[3]);
                    uint32_t kcb = g * 32 + ((lane >> 4) & 1) * 16;
                    #pragma unroll
                    for (int db2 = 0; db2 < 4; ++db2) {
                        uint32_t vaddr = vb + swz((uint32_t)((db2 * 16 + (lane & 15)) * 128) + kcb);
                        uint32_t vh[4], vl[4];
                        LDSM4(vh, vaddr);
                        LDSM4(vl, vaddr + 8192);
                        mma_bf16(oacc[db2 * 2],     ah, vh[0], vh[2]);
                        mma_bf16(oacc[db2 * 2],     ah, vl[0], vl[2]);
                        mma_bf16(oacc[db2 * 2],     al, vh[0], vh[2]);
                        mma_bf16(oacc[db2 * 2 + 1], ah, vh[1], vh[3]);
                        mma_bf16(oacc[db2 * 2 + 1], ah, vl[1], vl[3]);
                        mma_bf16(oacc[db2 * 2 + 1], al, vh[1], vh[3]);
                    }
                }
                __syncthreads();
            }
            #pragma unroll
            for (int db = 0; db < 8; ++db) {
                int col = db * 8 + 2 * (lane & 3);
                *reinterpret_cast<float2*>(out + ((size_t)bh * S + r0g) * Dh + col) =
                    make_float2(oacc[db][0], oacc[db][1]);
                *reinterpret_cast<float2*>(out + ((size_t)bh * S + r0g + 8) * Dh + col) =
                    make_float2(oacc[db][2], oacc[db][3]);
            }
        }
    }
}

extern "C" void kernel_launch(void* const* d_in, const int* in_sizes, int n_in,
                              void* d_out, int out_size) {
    const float* q = (const float*)d_in[0];
    const float* k = (const float*)d_in[1];
    const float* v = (const float*)d_in[2];
    const int* mask = (const int*)d_in[3];

    float* out = (float*)d_out;
    float* p_attn = out + (size_t)Bn * Hn * S * Dh;

    conv_qk<<<NELEM / 4 / THREADS, THREADS>>>(q, k);
    conv_vt<<<dim3(S / 32, Dh / 32, BH), dim3(32, 8)>>>(v);

    cudaFuncSetAttribute(attn_persist, cudaFuncAttributeMaxDynamicSharedMemorySize, SMEM_BYTES);
    attn_persist<<<GRID, THREADS, SMEM_BYTES>>>(mask, out, p_attn);
}